// round 13
// baseline (speedup 1.0000x reference)
#include <cuda_runtime.h>
#include <cuda_fp16.h>
#include <math.h>
#include <stdint.h>

// Problem constants
#define S_LEN  2048
#define HID    2048
#define NH     16
#define NKV    4
#define HD     128
#define KVDIM  512
#define QKVW   3072
#define K0     2048

// Scratch (device globals — no allocation allowed)
__device__ __half g_attnh[S_LEN * HID];          // attention output (fp16, A-side)
__device__ __half g_Xh[S_LEN * K0];              // X rounded fp16
__device__ __half g_Wqkvh[QKVW * K0];            // Wq|Wk|Wv fp16 (single-term)
__device__ __half g_Woh[HID * K0];               // Wo fp16 (single-term)
// attention operands
__device__ __half g_Qh[S_LEN * HID];             // scaled+rope q, rounded
__device__ __half g_Khi[S_LEN * KVDIM];
__device__ __half g_Klo[S_LEN * KVDIM];
__device__ __half g_Vhi[S_LEN * KVDIM];
__device__ __half g_Vlo[S_LEN * KVDIM];

// ---------------------------------------------------------------------------
// helpers
// ---------------------------------------------------------------------------
__device__ __forceinline__ uint32_t smem_u32(const void* p) {
    uint32_t a;
    asm("{ .reg .u64 t; cvta.to.shared.u64 t, %1; cvt.u32.u64 %0, t; }" : "=r"(a) : "l"(p));
    return a;
}
__device__ __forceinline__ void cpasync16(uint32_t s, const void* g) {
    asm volatile("cp.async.cg.shared.global [%0], [%1], 16;" :: "r"(s), "l"(g) : "memory");
}
__device__ __forceinline__ uint32_t swz(uint32_t off) {        // SW128 XOR swizzle
    return off ^ ((off >> 3) & 0x70);
}
__device__ __forceinline__ void ldsm4(uint32_t* r, uint32_t addr) {
    asm volatile("ldmatrix.sync.aligned.m8n8.x4.shared.b16 {%0,%1,%2,%3}, [%4];"
                 : "=r"(r[0]), "=r"(r[1]), "=r"(r[2]), "=r"(r[3]) : "r"(addr));
}
__device__ __forceinline__ void ldsm4t(uint32_t* r, uint32_t addr) {
    asm volatile("ldmatrix.sync.aligned.m8n8.x4.trans.shared.b16 {%0,%1,%2,%3}, [%4];"
                 : "=r"(r[0]), "=r"(r[1]), "=r"(r[2]), "=r"(r[3]) : "r"(addr));
}
__device__ __forceinline__ void mma_f16(float* d, const uint32_t* a, const uint32_t* b) {
    asm volatile(
        "mma.sync.aligned.m16n8k16.row.col.f32.f16.f16.f32 "
        "{%0,%1,%2,%3}, {%4,%5,%6,%7}, {%8,%9}, {%0,%1,%2,%3};"
        : "+f"(d[0]), "+f"(d[1]), "+f"(d[2]), "+f"(d[3])
        : "r"(a[0]), "r"(a[1]), "r"(a[2]), "r"(a[3]), "r"(b[0]), "r"(b[1]));
}
__device__ __forceinline__ uint32_t pack_h2(float lo, float hi) {
    __half2 t = __floats2half2_rn(lo, hi);
    return *reinterpret_cast<uint32_t*>(&t);
}

// ---------------------------------------------------------------------------
// One merged conversion kernel (row space: Wq|Wk|Wv|Wo|X, each row 2048 fp32)
// All outputs plain fp16 (single rounding).
// ---------------------------------------------------------------------------
#define CONV_N4 ((QKVW + HID + S_LEN) * (K0 / 4))

__global__ void convert_all(const float4* __restrict__ Wq, const float4* __restrict__ Wk,
                            const float4* __restrict__ Wv, const float4* __restrict__ Wo,
                            const float4* __restrict__ X) {
    int idx = blockIdx.x * 256 + threadIdx.x;
    if (idx >= CONV_N4) return;
    int e = idx * 4;
    int r = e >> 11;
    int c = e & (K0 - 1);

    const float4* src;
    __half* dst;
    if (r < HID) {
        src = Wq + (((size_t)r * K0 + c) >> 2);
        dst = g_Wqkvh + (size_t)r * K0 + c;
    } else if (r < HID + KVDIM) {
        src = Wk + (((size_t)(r - HID) * K0 + c) >> 2);
        dst = g_Wqkvh + (size_t)r * K0 + c;
    } else if (r < QKVW) {
        src = Wv + (((size_t)(r - HID - KVDIM) * K0 + c) >> 2);
        dst = g_Wqkvh + (size_t)r * K0 + c;
    } else if (r < QKVW + HID) {
        src = Wo + (((size_t)(r - QKVW) * K0 + c) >> 2);
        dst = g_Woh + (size_t)(r - QKVW) * K0 + c;
    } else {
        int xr = r - (QKVW + HID);
        src = X + (((size_t)xr * K0 + c) >> 2);
        dst = g_Xh + (size_t)xr * K0 + c;
    }
    float4 v = *src;
    __half2* o = (__half2*)dst;
    o[0] = __floats2half2_rn(v.x, v.y);
    o[1] = __floats2half2_rn(v.z, v.w);
}

// ---------------------------------------------------------------------------
// fp16 HMMA GEMM (single-term): C[bm+128, bn+128] = A B^T over K0=2048.
// CTA 128x128, KB=64, 8 warps (2x4), warp tile 64x32, 3-stage, 2 CTAs/SM.
// MODE 0: store fp32 C.  MODE 1: fused RoPE + fp16-split QKV epilogue.
// ---------------------------------------------------------------------------
#define KB      64
#define NKB     (K0 / KB)           // 32
#define STG     32768
#define GEMM_SMEM (3 * STG)         // 98304
#define SCW     132

template <int MODE>
__global__ __launch_bounds__(256)
void gemm_mma(const __half* __restrict__ A, const __half* __restrict__ B,
              float* __restrict__ C, int ldc) {
    extern __shared__ char dsm[];
    const uint32_t base = smem_u32(dsm);
    const int tid  = threadIdx.x;
    const int wid  = tid >> 5;
    const int lane = tid & 31;
    const int wm   = wid >> 2;
    const int wn   = wid & 3;
    const int quad = lane >> 3;
    const int l8   = lane & 7;
    const int bm = blockIdx.y * 128;
    const int bn = blockIdx.x * 128;

    const __half* Abase = A + (size_t)bm * K0;
    const __half* Bbase = B + (size_t)bn * K0;

    float acc[4][4][4];
#pragma unroll
    for (int i = 0; i < 4; i++)
#pragma unroll
        for (int j = 0; j < 4; j++)
#pragma unroll
            for (int v = 0; v < 4; v++) acc[i][j][v] = 0.f;

    int a_row[4], b_row[2];
#pragma unroll
    for (int mi = 0; mi < 4; mi++) a_row[mi] = wm * 64 + mi * 16 + (quad & 1) * 8 + l8;
#pragma unroll
    for (int n2 = 0; n2 < 2; n2++) b_row[n2] = wn * 32 + n2 * 16 + (quad >> 1) * 8 + l8;
    const int a_koff = (quad >> 1) * 16;
    const int b_koff = (quad & 1) * 16;

    const int ld_r = tid >> 3;
    const int ld_c = (tid & 7) * 8;

    auto issue_loads = [&](int kb, int buf) {
        const __half* ag = Abase + (size_t)ld_r * K0 + kb * KB + ld_c;
        const __half* bg = Bbase + (size_t)ld_r * K0 + kb * KB + ld_c;
        const uint32_t sa = base + buf * STG;
        const uint32_t sb = sa + 16384;
#pragma unroll
        for (int i = 0; i < 4; i++) {
            uint32_t s = swz((uint32_t)((ld_r + i * 32) * 128 + ld_c * 2));
            cpasync16(sa + s, ag + (size_t)i * 32 * K0);
            cpasync16(sb + s, bg + (size_t)i * 32 * K0);
        }
        asm volatile("cp.async.commit_group;" ::: "memory");
    };

    issue_loads(0, 0);
    issue_loads(1, 1);

    for (int kb = 0; kb < NKB; kb++) {
        const int buf = kb % 3;
        if (kb + 2 < NKB) {
            issue_loads(kb + 2, (kb + 2) % 3);
            asm volatile("cp.async.wait_group 2;" ::: "memory");
        } else if (kb + 1 < NKB) {
            asm volatile("cp.async.wait_group 1;" ::: "memory");
        } else {
            asm volatile("cp.async.wait_group 0;" ::: "memory");
        }
        __syncthreads();

        const uint32_t As = base + buf * STG;
        const uint32_t Bs = As + 16384;
#pragma unroll
        for (int ks = 0; ks < 4; ks++) {
            uint32_t af[4][4], bf[2][4];
#pragma unroll
            for (int mi = 0; mi < 4; mi++)
                ldsm4(af[mi], As + swz((uint32_t)(a_row[mi] * 128 + ks * 32 + a_koff)));
#pragma unroll
            for (int n2 = 0; n2 < 2; n2++)
                ldsm4(bf[n2], Bs + swz((uint32_t)(b_row[n2] * 128 + ks * 32 + b_koff)));
#pragma unroll
            for (int mi = 0; mi < 4; mi++) {
#pragma unroll
                for (int ni = 0; ni < 4; ni++) {
                    uint32_t bb[2] = { bf[ni >> 1][(ni & 1) * 2], bf[ni >> 1][(ni & 1) * 2 + 1] };
                    mma_f16(acc[mi][ni], af[mi], bb);
                }
            }
        }
        __syncthreads();
    }

    const int er = lane >> 2;
    const int ec = (lane & 3) * 2;

    if (MODE == 0) {
#pragma unroll
        for (int mi = 0; mi < 4; mi++) {
            int row0 = bm + wm * 64 + mi * 16 + er;
#pragma unroll
            for (int ni = 0; ni < 4; ni++) {
                int col = bn + wn * 32 + ni * 8 + ec;
                *(float2*)(C + (size_t)row0 * ldc + col) = make_float2(acc[mi][ni][0], acc[mi][ni][1]);
                *(float2*)(C + (size_t)(row0 + 8) * ldc + col) = make_float2(acc[mi][ni][2], acc[mi][ni][3]);
            }
        }
    } else {
        // ---- QKV epilogue: stage 128x128 fp32 tile, RoPE + fp16 split ----
        float* sC = (float*)dsm;
        const int bx = blockIdx.x;                    // 0..23
        const int region = (bx < 16) ? 0 : (bx < 20 ? 1 : 2);   // Q / K / V
        const float sscale = 0.08838834764831845f;
        __syncthreads();
#pragma unroll
        for (int mi = 0; mi < 4; mi++) {
            int rr = wm * 64 + mi * 16 + er;
#pragma unroll
            for (int ni = 0; ni < 4; ni++) {
                int col = wn * 32 + ni * 8 + ec;
                sC[rr * SCW + col] = acc[mi][ni][0];
                sC[rr * SCW + col + 1] = acc[mi][ni][1];
                sC[(rr + 8) * SCW + col] = acc[mi][ni][2];
                sC[(rr + 8) * SCW + col + 1] = acc[mi][ni][3];
            }
        }
        __syncthreads();
#pragma unroll 4
        for (int it = 0; it < 32; it++) {
            int idx = tid + it * 256;                 // 8192 pairs
            int r = idx >> 6;
            int j = idx & 63;
            float x0 = sC[r * SCW + j];
            float x1 = sC[r * SCW + j + 64];
            int s = bm + r;
            if (region == 0) {
                float freq = powf(10000.0f, -(float)(2 * j) / (float)HD);
                float sn, cs;
                sincosf((float)s * freq, &sn, &cs);
                float y0 = (x0 * cs - x1 * sn) * sscale;
                float y1 = (x1 * cs + x0 * sn) * sscale;
                g_Qh[(size_t)s * HID + bn + j] = __float2half(y0);
                g_Qh[(size_t)s * HID + bn + j + 64] = __float2half(y1);
            } else if (region == 1) {
                float freq = powf(10000.0f, -(float)(2 * j) / (float)HD);
                float sn, cs;
                sincosf((float)s * freq, &sn, &cs);
                float y0 = x0 * cs - x1 * sn;
                float y1 = x1 * cs + x0 * sn;
                int kc = bn - HID + j;
                __half h0 = __float2half(y0), h1 = __float2half(y1);
                g_Khi[(size_t)s * KVDIM + kc] = h0;
                g_Khi[(size_t)s * KVDIM + kc + 64] = h1;
                g_Klo[(size_t)s * KVDIM + kc] = __float2half(y0 - __half2float(h0));
                g_Klo[(size_t)s * KVDIM + kc + 64] = __float2half(y1 - __half2float(h1));
            } else {
                int vc = bn - HID - KVDIM + j;
                __half h0 = __float2half(x0), h1 = __float2half(x1);
                g_Vhi[(size_t)s * KVDIM + vc] = h0;
                g_Vhi[(size_t)s * KVDIM + vc + 64] = h1;
                g_Vlo[(size_t)s * KVDIM + vc] = __float2half(x0 - __half2float(h0));
                g_Vlo[(size_t)s * KVDIM + vc + 64] = __float2half(x1 - __half2float(h1));
            }
        }
    }
}

// ---------------------------------------------------------------------------
// HMMA flash attention (causal, GQA), fp16 2-term (unchanged from R11).
// CTA = 128 threads (4 warps), 64 q-rows; KV tile 32, double-buffered.
// smem = 80KB -> 2 CTAs/SM.
// ---------------------------------------------------------------------------
#define Q_OFF 0
#define KVB_OFF(b) (16384 + (b) * 32768)
#define KHI_O 0
#define KLO_O 8192
#define VHI_O 16384
#define VLO_O 24576
#define FLASH_SMEM 81920

__global__ __launch_bounds__(128)
void flash_mma(const __half* __restrict__ Qp,
               const __half* __restrict__ Kh, const __half* __restrict__ Kl,
               const __half* __restrict__ Vh, const __half* __restrict__ Vl,
               __half* __restrict__ attn_out) {
    extern __shared__ char dsm[];
    const uint32_t base = smem_u32(dsm);
    const int tid  = threadIdx.x;
    const int lane = tid & 31;
    const int warp = tid >> 5;
    const int qt   = (int)gridDim.x - 1 - (int)blockIdx.x;   // big tiles first
    const int h    = blockIdx.y;
    const int kvh  = h >> 2;
    const int wrow = warp * 16;
    const int nt   = 2 * qt + 2;
    const int q_row0 = qt * 64;

    const int rr = tid >> 4;
    const int cc = (tid & 15) * 8;
    const int panel = cc >> 6;
    const int col = cc & 63;

    {
        const __half* qg = Qp + (size_t)q_row0 * HID + h * HD + cc;
#pragma unroll
        for (int i = 0; i < 8; i++) {
            int r = rr + i * 8;
            uint32_t d = panel * 8192 + swz((uint32_t)(r * 128 + col * 2));
            cpasync16(base + Q_OFF + d, qg + (size_t)r * HID);
        }
    }
    auto issue_kv = [&](int kb, int buf) {
        const uint32_t kvb = base + KVB_OFF(buf);
#pragma unroll
        for (int i = 0; i < 4; i++) {
            int r = rr + i * 8;
            uint32_t d = panel * 4096 + swz((uint32_t)(r * 128 + col * 2));
            size_t g = (size_t)(kb * 32 + r) * KVDIM + kvh * HD + cc;
            cpasync16(kvb + KHI_O + d, Kh + g);
            cpasync16(kvb + KLO_O + d, Kl + g);
            cpasync16(kvb + VHI_O + d, Vh + g);
            cpasync16(kvb + VLO_O + d, Vl + g);
        }
        asm volatile("cp.async.commit_group;" ::: "memory");
    };
    issue_kv(0, 0);
    asm volatile("cp.async.wait_group 0;" ::: "memory");
    __syncthreads();

    auto ldQ = [&](int ks, uint32_t* a) {
        int row = wrow + (lane & 15);
        int kc = (16 * ks) & 63;
        uint32_t addr = base + Q_OFF + (ks >> 2) * 8192 +
                        swz((uint32_t)(row * 128 + (kc + (lane >> 4) * 8) * 2));
        ldsm4(a, addr);
    };
    auto ldK = [&](uint32_t arr, int ks, int nb, uint32_t* b) {
        int row = nb * 16 + (lane & 7) + ((lane >> 4) << 3);
        int kc = (16 * ks) & 63;
        int kadd = ((lane >> 3) & 1) * 8;
        uint32_t addr = base + arr + (ks >> 2) * 4096 +
                        swz((uint32_t)(row * 128 + (kc + kadd) * 2));
        ldsm4(b, addr);
    };
    auto ldV = [&](uint32_t arr, int ks, int db, uint32_t* b) {
        int row = ks * 16 + (lane & 7) + (((lane >> 3) & 1) << 3);
        int dc = (16 * db) & 63;
        int dadd = (lane >> 4) * 8;
        uint32_t addr = base + arr + (db >> 2) * 4096 +
                        swz((uint32_t)(row * 128 + (dc + dadd) * 2));
        ldsm4t(b, addr);
    };

    float oacc[16][4];
#pragma unroll
    for (int i = 0; i < 16; i++)
#pragma unroll
        for (int v = 0; v < 4; v++) oacc[i][v] = 0.f;
    float ml[2] = {-1e30f, -1e30f};
    float ll[2] = {0.f, 0.f};

    for (int kb = 0; kb < nt; kb++) {
        const int buf = kb & 1;
        if (kb + 1 < nt) {
            issue_kv(kb + 1, buf ^ 1);
            asm volatile("cp.async.wait_group 1;" ::: "memory");
        } else {
            asm volatile("cp.async.wait_group 0;" ::: "memory");
        }
        __syncthreads();

        const uint32_t kvb = KVB_OFF(buf);

        float pacc[4][4];
#pragma unroll
        for (int i = 0; i < 4; i++)
#pragma unroll
            for (int v = 0; v < 4; v++) pacc[i][v] = 0.f;

#pragma unroll
        for (int ks = 0; ks < 8; ks++) {
            uint32_t aq[4];
            ldQ(ks, aq);
#pragma unroll
            for (int nb = 0; nb < 2; nb++) {
                uint32_t bh[4], bl[4];
                ldK(kvb + KHI_O, ks, nb, bh);
                ldK(kvb + KLO_O, ks, nb, bl);
                mma_f16(pacc[2 * nb],     aq, bh);
                mma_f16(pacc[2 * nb + 1], aq, bh + 2);
                mma_f16(pacc[2 * nb],     aq, bl);
                mma_f16(pacc[2 * nb + 1], aq, bl + 2);
            }
        }

        if (kb >= 2 * qt) {
            int r0 = q_row0 + wrow + (lane >> 2);
#pragma unroll
            for (int ni = 0; ni < 4; ni++) {
                int c0 = kb * 32 + ni * 8 + (lane & 3) * 2;
                if (c0     > r0)     pacc[ni][0] = -1e30f;
                if (c0 + 1 > r0)     pacc[ni][1] = -1e30f;
                if (c0     > r0 + 8) pacc[ni][2] = -1e30f;
                if (c0 + 1 > r0 + 8) pacc[ni][3] = -1e30f;
            }
        }

        float mx0 = -1e30f, mx1 = -1e30f;
#pragma unroll
        for (int ni = 0; ni < 4; ni++) {
            mx0 = fmaxf(mx0, fmaxf(pacc[ni][0], pacc[ni][1]));
            mx1 = fmaxf(mx1, fmaxf(pacc[ni][2], pacc[ni][3]));
        }
        mx0 = fmaxf(mx0, __shfl_xor_sync(0xffffffffu, mx0, 1));
        mx0 = fmaxf(mx0, __shfl_xor_sync(0xffffffffu, mx0, 2));
        mx1 = fmaxf(mx1, __shfl_xor_sync(0xffffffffu, mx1, 1));
        mx1 = fmaxf(mx1, __shfl_xor_sync(0xffffffffu, mx1, 2));
        float mn0 = fmaxf(ml[0], mx0);
        float mn1 = fmaxf(ml[1], mx1);
        float sc0 = __expf(ml[0] - mn0);
        float sc1 = __expf(ml[1] - mn1);

        uint32_t phi[8];
        float ps0 = 0.f, ps1 = 0.f;
#pragma unroll
        for (int ni = 0; ni < 4; ni++) {
            float p0 = __expf(pacc[ni][0] - mn0);
            float p1 = __expf(pacc[ni][1] - mn0);
            float p2 = __expf(pacc[ni][2] - mn1);
            float p3 = __expf(pacc[ni][3] - mn1);
            ps0 += p0 + p1;
            ps1 += p2 + p3;
            phi[2 * ni]     = pack_h2(p0, p1);
            phi[2 * ni + 1] = pack_h2(p2, p3);
        }
        ps0 += __shfl_xor_sync(0xffffffffu, ps0, 1);
        ps0 += __shfl_xor_sync(0xffffffffu, ps0, 2);
        ps1 += __shfl_xor_sync(0xffffffffu, ps1, 1);
        ps1 += __shfl_xor_sync(0xffffffffu, ps1, 2);
        ll[0] = ll[0] * sc0 + ps0;
        ll[1] = ll[1] * sc1 + ps1;
        ml[0] = mn0; ml[1] = mn1;
#pragma unroll
        for (int ni = 0; ni < 16; ni++) {
            oacc[ni][0] *= sc0; oacc[ni][1] *= sc0;
            oacc[ni][2] *= sc1; oacc[ni][3] *= sc1;
        }

#pragma unroll
        for (int ks = 0; ks < 2; ks++) {
            uint32_t aph[4] = { phi[4 * ks], phi[4 * ks + 1], phi[4 * ks + 2], phi[4 * ks + 3] };
#pragma unroll
            for (int db = 0; db < 8; db++) {
                uint32_t bh[4], bl[4];
                ldV(kvb + VHI_O, ks, db, bh);
                mma_f16(oacc[2 * db],     aph, bh);
                mma_f16(oacc[2 * db + 1], aph, bh + 2);
                ldV(kvb + VLO_O, ks, db, bl);
                mma_f16(oacc[2 * db],     aph, bl);
                mma_f16(oacc[2 * db + 1], aph, bl + 2);
            }
        }
        __syncthreads();
    }

    float inv0 = 1.0f / ll[0];
    float inv1 = 1.0f / ll[1];
    int row0 = q_row0 + wrow + (lane >> 2);
#pragma unroll
    for (int ni = 0; ni < 16; ni++) {
        int col = h * HD + ni * 8 + (lane & 3) * 2;
        __half2 v0 = __floats2half2_rn(oacc[ni][0] * inv0, oacc[ni][1] * inv0);
        __half2 v1 = __floats2half2_rn(oacc[ni][2] * inv1, oacc[ni][3] * inv1);
        *(__half2*)(attn_out + (size_t)row0 * HID + col) = v0;
        *(__half2*)(attn_out + (size_t)(row0 + 8) * HID + col) = v1;
    }
}

// ---------------------------------------------------------------------------
extern "C" void kernel_launch(void* const* d_in, const int* in_sizes, int n_in,
                              void* d_out, int out_size) {
    const float* X  = (const float*)d_in[0];
    const float* Wq = (const float*)d_in[1];
    const float* Wk = (const float*)d_in[2];
    const float* Wv = (const float*)d_in[3];
    const float* Wo = (const float*)d_in[4];
    float* out = (float*)d_out;

    void* p;
    cudaGetSymbolAddress(&p, g_attnh);  __half* attnh = (__half*)p;
    cudaGetSymbolAddress(&p, g_Xh);     __half* Xh    = (__half*)p;
    cudaGetSymbolAddress(&p, g_Wqkvh);  __half* Wqkvh = (__half*)p;
    cudaGetSymbolAddress(&p, g_Woh);    __half* Woh   = (__half*)p;
    __half *Qh, *Kh, *Kl, *Vh, *Vl;
    cudaGetSymbolAddress(&p, g_Qh);  Qh = (__half*)p;
    cudaGetSymbolAddress(&p, g_Khi); Kh = (__half*)p;
    cudaGetSymbolAddress(&p, g_Klo); Kl = (__half*)p;
    cudaGetSymbolAddress(&p, g_Vhi); Vh = (__half*)p;
    cudaGetSymbolAddress(&p, g_Vlo); Vl = (__half*)p;

    cudaFuncSetAttribute(gemm_mma<0>, cudaFuncAttributeMaxDynamicSharedMemorySize, GEMM_SMEM);
    cudaFuncSetAttribute(gemm_mma<1>, cudaFuncAttributeMaxDynamicSharedMemorySize, GEMM_SMEM);
    cudaFuncSetAttribute(flash_mma, cudaFuncAttributeMaxDynamicSharedMemorySize, FLASH_SMEM);

    // all conversions in one launch (plain fp16 everywhere)
    convert_all<<<(CONV_N4 + 255) / 256, 256>>>(
        (const float4*)Wq, (const float4*)Wk, (const float4*)Wv,
        (const float4*)Wo, (const float4*)X);

    // QKV projection with fused RoPE + split epilogue (single-term weights)
    gemm_mma<1><<<dim3(QKVW / 128, S_LEN / 128), 256, GEMM_SMEM>>>(Xh, Wqkvh, nullptr, 0);

    // HMMA causal flash attention -> fp16
    flash_mma<<<dim3(S_LEN / 64, NH), 128, FLASH_SMEM>>>(Qh, Kh, Kl, Vh, Vl, attnh);

    // Output projection (single-term weights)
    gemm_mma<0><<<dim3(HID / 128, S_LEN / 128), 256, GEMM_SMEM>>>(attnh, Woh, out, HID);
}

// round 14
// speedup vs baseline: 1.2709x; 1.2709x over previous
#include <cuda_runtime.h>
#include <cuda_fp16.h>
#include <math.h>
#include <stdint.h>

// Problem constants
#define S_LEN  2048
#define HID    2048
#define NH     16
#define NKV    4
#define HD     128
#define KVDIM  512
#define QKVW   3072
#define K0     2048
#define KC2    (2*K0)      // 4096: QKV B-side hi|lo concatenated K

// Scratch (device globals — no allocation allowed)
__device__ __half g_attnh[S_LEN * HID];          // attention output (fp16, A-side)
__device__ __half g_Xh[S_LEN * K0];              // X rounded fp16
__device__ __half g_Wqkv2[QKVW * KC2];           // Wq|Wk|Wv split [3072][hi|lo 4096]
__device__ __half g_Woh[HID * K0];               // Wo fp16 single-term
// attention operands
__device__ __half g_Qh[S_LEN * HID];             // scaled+rope q, rounded
__device__ __half g_Khi[S_LEN * KVDIM];
__device__ __half g_Klo[S_LEN * KVDIM];
__device__ __half g_Vhi[S_LEN * KVDIM];
__device__ __half g_Vlo[S_LEN * KVDIM];

// ---------------------------------------------------------------------------
// helpers
// ---------------------------------------------------------------------------
__device__ __forceinline__ uint32_t smem_u32(const void* p) {
    uint32_t a;
    asm("{ .reg .u64 t; cvta.to.shared.u64 t, %1; cvt.u32.u64 %0, t; }" : "=r"(a) : "l"(p));
    return a;
}
__device__ __forceinline__ void cpasync16(uint32_t s, const void* g) {
    asm volatile("cp.async.cg.shared.global [%0], [%1], 16;" :: "r"(s), "l"(g) : "memory");
}
__device__ __forceinline__ uint32_t swz(uint32_t off) {        // SW128 XOR swizzle
    return off ^ ((off >> 3) & 0x70);
}
__device__ __forceinline__ void ldsm4(uint32_t* r, uint32_t addr) {
    asm volatile("ldmatrix.sync.aligned.m8n8.x4.shared.b16 {%0,%1,%2,%3}, [%4];"
                 : "=r"(r[0]), "=r"(r[1]), "=r"(r[2]), "=r"(r[3]) : "r"(addr));
}
__device__ __forceinline__ void ldsm4t(uint32_t* r, uint32_t addr) {
    asm volatile("ldmatrix.sync.aligned.m8n8.x4.trans.shared.b16 {%0,%1,%2,%3}, [%4];"
                 : "=r"(r[0]), "=r"(r[1]), "=r"(r[2]), "=r"(r[3]) : "r"(addr));
}
__device__ __forceinline__ void mma_f16(float* d, const uint32_t* a, const uint32_t* b) {
    asm volatile(
        "mma.sync.aligned.m16n8k16.row.col.f32.f16.f16.f32 "
        "{%0,%1,%2,%3}, {%4,%5,%6,%7}, {%8,%9}, {%0,%1,%2,%3};"
        : "+f"(d[0]), "+f"(d[1]), "+f"(d[2]), "+f"(d[3])
        : "r"(a[0]), "r"(a[1]), "r"(a[2]), "r"(a[3]), "r"(b[0]), "r"(b[1]));
}
__device__ __forceinline__ uint32_t pack_h2(float lo, float hi) {
    __half2 t = __floats2half2_rn(lo, hi);
    return *reinterpret_cast<uint32_t*>(&t);
}

// ---------------------------------------------------------------------------
// Merged conversion kernel (row space: Wq|Wk|Wv split, Wo single, X single)
// ---------------------------------------------------------------------------
#define CONV_N4 ((QKVW + HID + S_LEN) * (K0 / 4))

__global__ void convert_all(const float4* __restrict__ Wq, const float4* __restrict__ Wk,
                            const float4* __restrict__ Wv, const float4* __restrict__ Wo,
                            const float4* __restrict__ X) {
    int idx = blockIdx.x * 256 + threadIdx.x;
    if (idx >= CONV_N4) return;
    int e = idx * 4;
    int r = e >> 11;
    int c = e & (K0 - 1);

    if (r >= QKVW) {                 // Wo or X: plain fp16 round
        const float4* src;
        __half* dst;
        if (r < QKVW + HID) {
            src = Wo + (((size_t)(r - QKVW) * K0 + c) >> 2);
            dst = g_Woh + (size_t)(r - QKVW) * K0 + c;
        } else {
            int xr = r - (QKVW + HID);
            src = X + (((size_t)xr * K0 + c) >> 2);
            dst = g_Xh + (size_t)xr * K0 + c;
        }
        float4 v = *src;
        __half2* o = (__half2*)dst;
        o[0] = __floats2half2_rn(v.x, v.y);
        o[1] = __floats2half2_rn(v.z, v.w);
        return;
    }

    const float4* src;
    if (r < HID)                 src = Wq + (((size_t)r * K0 + c) >> 2);
    else if (r < HID + KVDIM)    src = Wk + (((size_t)(r - HID) * K0 + c) >> 2);
    else                         src = Wv + (((size_t)(r - HID - KVDIM) * K0 + c) >> 2);
    __half* dst = g_Wqkv2 + (size_t)r * KC2;

    float4 v = *src;
    __half2 h01 = __floats2half2_rn(v.x, v.y);
    __half2 h23 = __floats2half2_rn(v.z, v.w);
    __half2 l01 = __floats2half2_rn(v.x - __low2float(h01), v.y - __high2float(h01));
    __half2 l23 = __floats2half2_rn(v.z - __low2float(h23), v.w - __high2float(h23));
    __half2* oh = (__half2*)(dst + c);
    __half2* ol = (__half2*)(dst + K0 + c);
    oh[0] = h01; oh[1] = h23;
    ol[0] = l01; ol[1] = l23;
}

// ---------------------------------------------------------------------------
// fp16 HMMA GEMM: C[bm+128, bn+128] = A B^T, B row stride = BSTRIDE elems,
// K range = BSTRIDE (NKB = BSTRIDE/KB); A column wraps mod K0.
// CTA 128x128, KB=64, 8 warps (2x4), warp tile 64x32, 3-stage, 2 CTAs/SM.
// MODE 0: store fp32 C.  MODE 1: fused RoPE + fp16-split QKV epilogue.
// ---------------------------------------------------------------------------
#define KB      64
#define STG     32768
#define GEMM_SMEM (3 * STG)         // 98304
#define SCW     132

template <int MODE, int BSTRIDE>
__global__ __launch_bounds__(256)
void gemm_mma(const __half* __restrict__ A, const __half* __restrict__ B,
              float* __restrict__ C, int ldc) {
    constexpr int NKB = BSTRIDE / KB;
    extern __shared__ char dsm[];
    const uint32_t base = smem_u32(dsm);
    const int tid  = threadIdx.x;
    const int wid  = tid >> 5;
    const int lane = tid & 31;
    const int wm   = wid >> 2;
    const int wn   = wid & 3;
    const int quad = lane >> 3;
    const int l8   = lane & 7;
    const int bm = blockIdx.y * 128;
    const int bn = blockIdx.x * 128;

    const __half* Abase = A + (size_t)bm * K0;
    const __half* Bbase = B + (size_t)bn * BSTRIDE;

    float acc[4][4][4];
#pragma unroll
    for (int i = 0; i < 4; i++)
#pragma unroll
        for (int j = 0; j < 4; j++)
#pragma unroll
            for (int v = 0; v < 4; v++) acc[i][j][v] = 0.f;

    int a_row[4], b_row[2];
#pragma unroll
    for (int mi = 0; mi < 4; mi++) a_row[mi] = wm * 64 + mi * 16 + (quad & 1) * 8 + l8;
#pragma unroll
    for (int n2 = 0; n2 < 2; n2++) b_row[n2] = wn * 32 + n2 * 16 + (quad >> 1) * 8 + l8;
    const int a_koff = (quad >> 1) * 16;
    const int b_koff = (quad & 1) * 16;

    const int ld_r = tid >> 3;
    const int ld_c = (tid & 7) * 8;

    auto issue_loads = [&](int kb, int buf) {
        const int a_col = (kb & 31) * KB + ld_c;     // wrap A over K0
        const __half* ag = Abase + (size_t)ld_r * K0 + a_col;
        const __half* bg = Bbase + (size_t)ld_r * BSTRIDE + kb * KB + ld_c;
        const uint32_t sa = base + buf * STG;
        const uint32_t sb = sa + 16384;
#pragma unroll
        for (int i = 0; i < 4; i++) {
            uint32_t s = swz((uint32_t)((ld_r + i * 32) * 128 + ld_c * 2));
            cpasync16(sa + s, ag + (size_t)i * 32 * K0);
            cpasync16(sb + s, bg + (size_t)i * 32 * BSTRIDE);
        }
        asm volatile("cp.async.commit_group;" ::: "memory");
    };

    issue_loads(0, 0);
    issue_loads(1, 1);

    for (int kb = 0; kb < NKB; kb++) {
        const int buf = kb % 3;
        if (kb + 2 < NKB) {
            issue_loads(kb + 2, (kb + 2) % 3);
            asm volatile("cp.async.wait_group 2;" ::: "memory");
        } else if (kb + 1 < NKB) {
            asm volatile("cp.async.wait_group 1;" ::: "memory");
        } else {
            asm volatile("cp.async.wait_group 0;" ::: "memory");
        }
        __syncthreads();

        const uint32_t As = base + buf * STG;
        const uint32_t Bs = As + 16384;
#pragma unroll
        for (int ks = 0; ks < 4; ks++) {
            uint32_t af[4][4], bf[2][4];
#pragma unroll
            for (int mi = 0; mi < 4; mi++)
                ldsm4(af[mi], As + swz((uint32_t)(a_row[mi] * 128 + ks * 32 + a_koff)));
#pragma unroll
            for (int n2 = 0; n2 < 2; n2++)
                ldsm4(bf[n2], Bs + swz((uint32_t)(b_row[n2] * 128 + ks * 32 + b_koff)));
#pragma unroll
            for (int mi = 0; mi < 4; mi++) {
#pragma unroll
                for (int ni = 0; ni < 4; ni++) {
                    uint32_t bb[2] = { bf[ni >> 1][(ni & 1) * 2], bf[ni >> 1][(ni & 1) * 2 + 1] };
                    mma_f16(acc[mi][ni], af[mi], bb);
                }
            }
        }
        __syncthreads();
    }

    const int er = lane >> 2;
    const int ec = (lane & 3) * 2;

    if (MODE == 0) {
#pragma unroll
        for (int mi = 0; mi < 4; mi++) {
            int row0 = bm + wm * 64 + mi * 16 + er;
#pragma unroll
            for (int ni = 0; ni < 4; ni++) {
                int col = bn + wn * 32 + ni * 8 + ec;
                *(float2*)(C + (size_t)row0 * ldc + col) = make_float2(acc[mi][ni][0], acc[mi][ni][1]);
                *(float2*)(C + (size_t)(row0 + 8) * ldc + col) = make_float2(acc[mi][ni][2], acc[mi][ni][3]);
            }
        }
    } else {
        // ---- QKV epilogue: stage 128x128 fp32 tile, RoPE + fp16 split ----
        float* sC = (float*)dsm;
        const int bx = blockIdx.x;                    // 0..23
        const int region = (bx < 16) ? 0 : (bx < 20 ? 1 : 2);   // Q / K / V
        const float sscale = 0.08838834764831845f;
        __syncthreads();
#pragma unroll
        for (int mi = 0; mi < 4; mi++) {
            int rr = wm * 64 + mi * 16 + er;
#pragma unroll
            for (int ni = 0; ni < 4; ni++) {
                int col = wn * 32 + ni * 8 + ec;
                sC[rr * SCW + col] = acc[mi][ni][0];
                sC[rr * SCW + col + 1] = acc[mi][ni][1];
                sC[(rr + 8) * SCW + col] = acc[mi][ni][2];
                sC[(rr + 8) * SCW + col + 1] = acc[mi][ni][3];
            }
        }
        __syncthreads();
#pragma unroll 4
        for (int it = 0; it < 32; it++) {
            int idx = tid + it * 256;                 // 8192 pairs
            int r = idx >> 6;
            int j = idx & 63;
            float x0 = sC[r * SCW + j];
            float x1 = sC[r * SCW + j + 64];
            int s = bm + r;
            if (region == 0) {
                float freq = powf(10000.0f, -(float)(2 * j) / (float)HD);
                float sn, cs;
                sincosf((float)s * freq, &sn, &cs);
                float y0 = (x0 * cs - x1 * sn) * sscale;
                float y1 = (x1 * cs + x0 * sn) * sscale;
                g_Qh[(size_t)s * HID + blockIdx.x * 128 + j] = __float2half(y0);
                g_Qh[(size_t)s * HID + blockIdx.x * 128 + j + 64] = __float2half(y1);
            } else if (region == 1) {
                float freq = powf(10000.0f, -(float)(2 * j) / (float)HD);
                float sn, cs;
                sincosf((float)s * freq, &sn, &cs);
                float y0 = x0 * cs - x1 * sn;
                float y1 = x1 * cs + x0 * sn;
                int kc = blockIdx.x * 128 - HID + j;
                __half h0 = __float2half(y0), h1 = __float2half(y1);
                g_Khi[(size_t)s * KVDIM + kc] = h0;
                g_Khi[(size_t)s * KVDIM + kc + 64] = h1;
                g_Klo[(size_t)s * KVDIM + kc] = __float2half(y0 - __half2float(h0));
                g_Klo[(size_t)s * KVDIM + kc + 64] = __float2half(y1 - __half2float(h1));
            } else {
                int vc = blockIdx.x * 128 - HID - KVDIM + j;
                __half h0 = __float2half(x0), h1 = __float2half(x1);
                g_Vhi[(size_t)s * KVDIM + vc] = h0;
                g_Vhi[(size_t)s * KVDIM + vc + 64] = h1;
                g_Vlo[(size_t)s * KVDIM + vc] = __float2half(x0 - __half2float(h0));
                g_Vlo[(size_t)s * KVDIM + vc + 64] = __float2half(x1 - __half2float(h1));
            }
        }
    }
}

// ---------------------------------------------------------------------------
// HMMA flash attention (causal, GQA), fp16 2-term (R11 proven, unchanged).
// CTA = 128 threads (4 warps), 64 q-rows; KV tile 32, double-buffered. 80KB.
// ---------------------------------------------------------------------------
#define Q_OFF 0
#define KVB_OFF(b) (16384 + (b) * 32768)
#define KHI_O 0
#define KLO_O 8192
#define VHI_O 16384
#define VLO_O 24576
#define FLASH_SMEM 81920

__global__ __launch_bounds__(128)
void flash_mma(const __half* __restrict__ Qp,
               const __half* __restrict__ Kh, const __half* __restrict__ Kl,
               const __half* __restrict__ Vh, const __half* __restrict__ Vl,
               __half* __restrict__ attn_out) {
    extern __shared__ char dsm[];
    const uint32_t base = smem_u32(dsm);
    const int tid  = threadIdx.x;
    const int lane = tid & 31;
    const int warp = tid >> 5;
    const int qt   = (int)gridDim.x - 1 - (int)blockIdx.x;
    const int h    = blockIdx.y;
    const int kvh  = h >> 2;
    const int wrow = warp * 16;
    const int nt   = 2 * qt + 2;
    const int q_row0 = qt * 64;

    const int rr = tid >> 4;
    const int cc = (tid & 15) * 8;
    const int panel = cc >> 6;
    const int col = cc & 63;

    {
        const __half* qg = Qp + (size_t)q_row0 * HID + h * HD + cc;
#pragma unroll
        for (int i = 0; i < 8; i++) {
            int r = rr + i * 8;
            uint32_t d = panel * 8192 + swz((uint32_t)(r * 128 + col * 2));
            cpasync16(base + Q_OFF + d, qg + (size_t)r * HID);
        }
    }
    auto issue_kv = [&](int kb, int buf) {
        const uint32_t kvb = base + KVB_OFF(buf);
#pragma unroll
        for (int i = 0; i < 4; i++) {
            int r = rr + i * 8;
            uint32_t d = panel * 4096 + swz((uint32_t)(r * 128 + col * 2));
            size_t g = (size_t)(kb * 32 + r) * KVDIM + kvh * HD + cc;
            cpasync16(kvb + KHI_O + d, Kh + g);
            cpasync16(kvb + KLO_O + d, Kl + g);
            cpasync16(kvb + VHI_O + d, Vh + g);
            cpasync16(kvb + VLO_O + d, Vl + g);
        }
        asm volatile("cp.async.commit_group;" ::: "memory");
    };
    issue_kv(0, 0);
    asm volatile("cp.async.wait_group 0;" ::: "memory");
    __syncthreads();

    auto ldQ = [&](int ks, uint32_t* a) {
        int row = wrow + (lane & 15);
        int kc = (16 * ks) & 63;
        uint32_t addr = base + Q_OFF + (ks >> 2) * 8192 +
                        swz((uint32_t)(row * 128 + (kc + (lane >> 4) * 8) * 2));
        ldsm4(a, addr);
    };
    auto ldK = [&](uint32_t arr, int ks, int nb, uint32_t* b) {
        int row = nb * 16 + (lane & 7) + ((lane >> 4) << 3);
        int kc = (16 * ks) & 63;
        int kadd = ((lane >> 3) & 1) * 8;
        uint32_t addr = base + arr + (ks >> 2) * 4096 +
                        swz((uint32_t)(row * 128 + (kc + kadd) * 2));
        ldsm4(b, addr);
    };
    auto ldV = [&](uint32_t arr, int ks, int db, uint32_t* b) {
        int row = ks * 16 + (lane & 7) + (((lane >> 3) & 1) << 3);
        int dc = (16 * db) & 63;
        int dadd = (lane >> 4) * 8;
        uint32_t addr = base + arr + (db >> 2) * 4096 +
                        swz((uint32_t)(row * 128 + (dc + dadd) * 2));
        ldsm4t(b, addr);
    };

    float oacc[16][4];
#pragma unroll
    for (int i = 0; i < 16; i++)
#pragma unroll
        for (int v = 0; v < 4; v++) oacc[i][v] = 0.f;
    float ml[2] = {-1e30f, -1e30f};
    float ll[2] = {0.f, 0.f};

    for (int kb = 0; kb < nt; kb++) {
        const int buf = kb & 1;
        if (kb + 1 < nt) {
            issue_kv(kb + 1, buf ^ 1);
            asm volatile("cp.async.wait_group 1;" ::: "memory");
        } else {
            asm volatile("cp.async.wait_group 0;" ::: "memory");
        }
        __syncthreads();

        const uint32_t kvb = KVB_OFF(buf);

        float pacc[4][4];
#pragma unroll
        for (int i = 0; i < 4; i++)
#pragma unroll
            for (int v = 0; v < 4; v++) pacc[i][v] = 0.f;

#pragma unroll
        for (int ks = 0; ks < 8; ks++) {
            uint32_t aq[4];
            ldQ(ks, aq);
#pragma unroll
            for (int nb = 0; nb < 2; nb++) {
                uint32_t bh[4], bl[4];
                ldK(kvb + KHI_O, ks, nb, bh);
                ldK(kvb + KLO_O, ks, nb, bl);
                mma_f16(pacc[2 * nb],     aq, bh);
                mma_f16(pacc[2 * nb + 1], aq, bh + 2);
                mma_f16(pacc[2 * nb],     aq, bl);
                mma_f16(pacc[2 * nb + 1], aq, bl + 2);
            }
        }

        if (kb >= 2 * qt) {
            int r0 = q_row0 + wrow + (lane >> 2);
#pragma unroll
            for (int ni = 0; ni < 4; ni++) {
                int c0 = kb * 32 + ni * 8 + (lane & 3) * 2;
                if (c0     > r0)     pacc[ni][0] = -1e30f;
                if (c0 + 1 > r0)     pacc[ni][1] = -1e30f;
                if (c0     > r0 + 8) pacc[ni][2] = -1e30f;
                if (c0 + 1 > r0 + 8) pacc[ni][3] = -1e30f;
            }
        }

        float mx0 = -1e30f, mx1 = -1e30f;
#pragma unroll
        for (int ni = 0; ni < 4; ni++) {
            mx0 = fmaxf(mx0, fmaxf(pacc[ni][0], pacc[ni][1]));
            mx1 = fmaxf(mx1, fmaxf(pacc[ni][2], pacc[ni][3]));
        }
        mx0 = fmaxf(mx0, __shfl_xor_sync(0xffffffffu, mx0, 1));
        mx0 = fmaxf(mx0, __shfl_xor_sync(0xffffffffu, mx0, 2));
        mx1 = fmaxf(mx1, __shfl_xor_sync(0xffffffffu, mx1, 1));
        mx1 = fmaxf(mx1, __shfl_xor_sync(0xffffffffu, mx1, 2));
        float mn0 = fmaxf(ml[0], mx0);
        float mn1 = fmaxf(ml[1], mx1);
        float sc0 = __expf(ml[0] - mn0);
        float sc1 = __expf(ml[1] - mn1);

        uint32_t phi[8];
        float ps0 = 0.f, ps1 = 0.f;
#pragma unroll
        for (int ni = 0; ni < 4; ni++) {
            float p0 = __expf(pacc[ni][0] - mn0);
            float p1 = __expf(pacc[ni][1] - mn0);
            float p2 = __expf(pacc[ni][2] - mn1);
            float p3 = __expf(pacc[ni][3] - mn1);
            ps0 += p0 + p1;
            ps1 += p2 + p3;
            phi[2 * ni]     = pack_h2(p0, p1);
            phi[2 * ni + 1] = pack_h2(p2, p3);
        }
        ps0 += __shfl_xor_sync(0xffffffffu, ps0, 1);
        ps0 += __shfl_xor_sync(0xffffffffu, ps0, 2);
        ps1 += __shfl_xor_sync(0xffffffffu, ps1, 1);
        ps1 += __shfl_xor_sync(0xffffffffu, ps1, 2);
        ll[0] = ll[0] * sc0 + ps0;
        ll[1] = ll[1] * sc1 + ps1;
        ml[0] = mn0; ml[1] = mn1;
#pragma unroll
        for (int ni = 0; ni < 16; ni++) {
            oacc[ni][0] *= sc0; oacc[ni][1] *= sc0;
            oacc[ni][2] *= sc1; oacc[ni][3] *= sc1;
        }

#pragma unroll
        for (int ks = 0; ks < 2; ks++) {
            uint32_t aph[4] = { phi[4 * ks], phi[4 * ks + 1], phi[4 * ks + 2], phi[4 * ks + 3] };
#pragma unroll
            for (int db = 0; db < 8; db++) {
                uint32_t bh[4], bl[4];
                ldV(kvb + VHI_O, ks, db, bh);
                mma_f16(oacc[2 * db],     aph, bh);
                mma_f16(oacc[2 * db + 1], aph, bh + 2);
                ldV(kvb + VLO_O, ks, db, bl);
                mma_f16(oacc[2 * db],     aph, bl);
                mma_f16(oacc[2 * db + 1], aph, bl + 2);
            }
        }
        __syncthreads();
    }

    float inv0 = 1.0f / ll[0];
    float inv1 = 1.0f / ll[1];
    int row0 = q_row0 + wrow + (lane >> 2);
#pragma unroll
    for (int ni = 0; ni < 16; ni++) {
        int col = h * HD + ni * 8 + (lane & 3) * 2;
        __half2 v0 = __floats2half2_rn(oacc[ni][0] * inv0, oacc[ni][1] * inv0);
        __half2 v1 = __floats2half2_rn(oacc[ni][2] * inv1, oacc[ni][3] * inv1);
        *(__half2*)(attn_out + (size_t)row0 * HID + col) = v0;
        *(__half2*)(attn_out + (size_t)(row0 + 8) * HID + col) = v1;
    }
}

// ---------------------------------------------------------------------------
extern "C" void kernel_launch(void* const* d_in, const int* in_sizes, int n_in,
                              void* d_out, int out_size) {
    const float* X  = (const float*)d_in[0];
    const float* Wq = (const float*)d_in[1];
    const float* Wk = (const float*)d_in[2];
    const float* Wv = (const float*)d_in[3];
    const float* Wo = (const float*)d_in[4];
    float* out = (float*)d_out;

    void* p;
    cudaGetSymbolAddress(&p, g_attnh);  __half* attnh = (__half*)p;
    cudaGetSymbolAddress(&p, g_Xh);     __half* Xh    = (__half*)p;
    cudaGetSymbolAddress(&p, g_Wqkv2);  __half* Wqkv2 = (__half*)p;
    cudaGetSymbolAddress(&p, g_Woh);    __half* Woh   = (__half*)p;
    __half *Qh, *Kh, *Kl, *Vh, *Vl;
    cudaGetSymbolAddress(&p, g_Qh);  Qh = (__half*)p;
    cudaGetSymbolAddress(&p, g_Khi); Kh = (__half*)p;
    cudaGetSymbolAddress(&p, g_Klo); Kl = (__half*)p;
    cudaGetSymbolAddress(&p, g_Vhi); Vh = (__half*)p;
    cudaGetSymbolAddress(&p, g_Vlo); Vl = (__half*)p;

    cudaFuncSetAttribute((const void*)gemm_mma<0, K0>,
                         cudaFuncAttributeMaxDynamicSharedMemorySize, GEMM_SMEM);
    cudaFuncSetAttribute((const void*)gemm_mma<1, KC2>,
                         cudaFuncAttributeMaxDynamicSharedMemorySize, GEMM_SMEM);
    cudaFuncSetAttribute(flash_mma, cudaFuncAttributeMaxDynamicSharedMemorySize, FLASH_SMEM);

    // all conversions in one launch
    convert_all<<<(CONV_N4 + 255) / 256, 256>>>(
        (const float4*)Wq, (const float4*)Wk, (const float4*)Wv,
        (const float4*)Wo, (const float4*)X);

    // QKV projection: 2-term split weights (R11 proven) + fused RoPE epilogue
    gemm_mma<1, KC2><<<dim3(QKVW / 128, S_LEN / 128), 256, GEMM_SMEM>>>(Xh, Wqkv2, nullptr, 0);

    // HMMA causal flash attention -> fp16
    flash_mma<<<dim3(S_LEN / 64, NH), 128, FLASH_SMEM>>>(Qh, Kh, Kl, Vh, Vl, attnh);

    // Output projection: single-term weights (measured faster: 92 -> 76 us)
    gemm_mma<0, K0><<<dim3(HID / 128, S_LEN / 128), 256, GEMM_SMEM>>>(attnh, Woh, out, HID);
}

// round 15
// speedup vs baseline: 1.5358x; 1.2084x over previous
#include <cuda_runtime.h>
#include <cuda_fp16.h>
#include <math.h>
#include <stdint.h>

// Problem constants
#define S_LEN  2048
#define HID    2048
#define NH     16
#define NKV    4
#define HD     128
#define KVDIM  512
#define QKVW   3072
#define K0     2048

// Scratch (device globals — no allocation allowed)
__device__ __half g_attnh[S_LEN * HID];          // attention output (fp16, A-side)
__device__ __half g_Xh[S_LEN * K0];              // X rounded fp16
__device__ __half g_Wqkvh[QKVW * K0];            // Wq|Wk|Wv fp16 single-term
__device__ __half g_Woh[HID * K0];               // Wo fp16 single-term
// attention operands
__device__ __half g_Qh[S_LEN * HID];             // scaled+rope q, rounded
__device__ __half g_Khi[S_LEN * KVDIM];
__device__ __half g_Klo[S_LEN * KVDIM];
__device__ __half g_Vhi[S_LEN * KVDIM];
__device__ __half g_Vlo[S_LEN * KVDIM];

// ---------------------------------------------------------------------------
// helpers
// ---------------------------------------------------------------------------
__device__ __forceinline__ uint32_t smem_u32(const void* p) {
    uint32_t a;
    asm("{ .reg .u64 t; cvta.to.shared.u64 t, %1; cvt.u32.u64 %0, t; }" : "=r"(a) : "l"(p));
    return a;
}
__device__ __forceinline__ void cpasync16(uint32_t s, const void* g) {
    asm volatile("cp.async.cg.shared.global [%0], [%1], 16;" :: "r"(s), "l"(g) : "memory");
}
__device__ __forceinline__ uint32_t swz(uint32_t off) {        // SW128 XOR swizzle
    return off ^ ((off >> 3) & 0x70);
}
__device__ __forceinline__ void ldsm4(uint32_t* r, uint32_t addr) {
    asm volatile("ldmatrix.sync.aligned.m8n8.x4.shared.b16 {%0,%1,%2,%3}, [%4];"
                 : "=r"(r[0]), "=r"(r[1]), "=r"(r[2]), "=r"(r[3]) : "r"(addr));
}
__device__ __forceinline__ void ldsm4t(uint32_t* r, uint32_t addr) {
    asm volatile("ldmatrix.sync.aligned.m8n8.x4.trans.shared.b16 {%0,%1,%2,%3}, [%4];"
                 : "=r"(r[0]), "=r"(r[1]), "=r"(r[2]), "=r"(r[3]) : "r"(addr));
}
__device__ __forceinline__ void mma_f16(float* d, const uint32_t* a, const uint32_t* b) {
    asm volatile(
        "mma.sync.aligned.m16n8k16.row.col.f32.f16.f16.f32 "
        "{%0,%1,%2,%3}, {%4,%5,%6,%7}, {%8,%9}, {%0,%1,%2,%3};"
        : "+f"(d[0]), "+f"(d[1]), "+f"(d[2]), "+f"(d[3])
        : "r"(a[0]), "r"(a[1]), "r"(a[2]), "r"(a[3]), "r"(b[0]), "r"(b[1]));
}
__device__ __forceinline__ uint32_t pack_h2(float lo, float hi) {
    __half2 t = __floats2half2_rn(lo, hi);
    return *reinterpret_cast<uint32_t*>(&t);
}

// ---------------------------------------------------------------------------
// Merged conversion kernel (row space: Wq|Wk|Wv|Wo|X, all plain fp16 round)
// ---------------------------------------------------------------------------
#define CONV_N4 ((QKVW + HID + S_LEN) * (K0 / 4))

__global__ void convert_all(const float4* __restrict__ Wq, const float4* __restrict__ Wk,
                            const float4* __restrict__ Wv, const float4* __restrict__ Wo,
                            const float4* __restrict__ X) {
    int idx = blockIdx.x * 256 + threadIdx.x;
    if (idx >= CONV_N4) return;
    int e = idx * 4;
    int r = e >> 11;
    int c = e & (K0 - 1);

    const float4* src;
    __half* dst;
    if (r < HID) {
        src = Wq + (((size_t)r * K0 + c) >> 2);
        dst = g_Wqkvh + (size_t)r * K0 + c;
    } else if (r < HID + KVDIM) {
        src = Wk + (((size_t)(r - HID) * K0 + c) >> 2);
        dst = g_Wqkvh + (size_t)r * K0 + c;
    } else if (r < QKVW) {
        src = Wv + (((size_t)(r - HID - KVDIM) * K0 + c) >> 2);
        dst = g_Wqkvh + (size_t)r * K0 + c;
    } else if (r < QKVW + HID) {
        src = Wo + (((size_t)(r - QKVW) * K0 + c) >> 2);
        dst = g_Woh + (size_t)(r - QKVW) * K0 + c;
    } else {
        int xr = r - (QKVW + HID);
        src = X + (((size_t)xr * K0 + c) >> 2);
        dst = g_Xh + (size_t)xr * K0 + c;
    }
    float4 v = *src;
    __half2* o = (__half2*)dst;
    o[0] = __floats2half2_rn(v.x, v.y);
    o[1] = __floats2half2_rn(v.z, v.w);
}

// ---------------------------------------------------------------------------
// fp16 HMMA GEMM (single-term): C[bm+128, bn+128] = A B^T over K0=2048.
// CTA 128x128, KB=64, 8 warps (2x4), warp tile 64x32, 3-stage, 2 CTAs/SM.
// MODE 0: store fp32 C.  MODE 1: fused RoPE + fp16-split QKV epilogue.
// ---------------------------------------------------------------------------
#define KB      64
#define NKB     (K0 / KB)           // 32
#define STG     32768
#define GEMM_SMEM (3 * STG)         // 98304
#define SCW     132

template <int MODE>
__global__ __launch_bounds__(256)
void gemm_mma(const __half* __restrict__ A, const __half* __restrict__ B,
              float* __restrict__ C, int ldc) {
    extern __shared__ char dsm[];
    const uint32_t base = smem_u32(dsm);
    const int tid  = threadIdx.x;
    const int wid  = tid >> 5;
    const int lane = tid & 31;
    const int wm   = wid >> 2;
    const int wn   = wid & 3;
    const int quad = lane >> 3;
    const int l8   = lane & 7;
    const int bm = blockIdx.y * 128;
    const int bn = blockIdx.x * 128;

    const __half* Abase = A + (size_t)bm * K0;
    const __half* Bbase = B + (size_t)bn * K0;

    float acc[4][4][4];
#pragma unroll
    for (int i = 0; i < 4; i++)
#pragma unroll
        for (int j = 0; j < 4; j++)
#pragma unroll
            for (int v = 0; v < 4; v++) acc[i][j][v] = 0.f;

    int a_row[4], b_row[2];
#pragma unroll
    for (int mi = 0; mi < 4; mi++) a_row[mi] = wm * 64 + mi * 16 + (quad & 1) * 8 + l8;
#pragma unroll
    for (int n2 = 0; n2 < 2; n2++) b_row[n2] = wn * 32 + n2 * 16 + (quad >> 1) * 8 + l8;
    const int a_koff = (quad >> 1) * 16;
    const int b_koff = (quad & 1) * 16;

    const int ld_r = tid >> 3;
    const int ld_c = (tid & 7) * 8;

    auto issue_loads = [&](int kb, int buf) {
        const __half* ag = Abase + (size_t)ld_r * K0 + kb * KB + ld_c;
        const __half* bg = Bbase + (size_t)ld_r * K0 + kb * KB + ld_c;
        const uint32_t sa = base + buf * STG;
        const uint32_t sb = sa + 16384;
#pragma unroll
        for (int i = 0; i < 4; i++) {
            uint32_t s = swz((uint32_t)((ld_r + i * 32) * 128 + ld_c * 2));
            cpasync16(sa + s, ag + (size_t)i * 32 * K0);
            cpasync16(sb + s, bg + (size_t)i * 32 * K0);
        }
        asm volatile("cp.async.commit_group;" ::: "memory");
    };

    issue_loads(0, 0);
    issue_loads(1, 1);

    for (int kb = 0; kb < NKB; kb++) {
        const int buf = kb % 3;
        if (kb + 2 < NKB) {
            issue_loads(kb + 2, (kb + 2) % 3);
            asm volatile("cp.async.wait_group 2;" ::: "memory");
        } else if (kb + 1 < NKB) {
            asm volatile("cp.async.wait_group 1;" ::: "memory");
        } else {
            asm volatile("cp.async.wait_group 0;" ::: "memory");
        }
        __syncthreads();

        const uint32_t As = base + buf * STG;
        const uint32_t Bs = As + 16384;
#pragma unroll
        for (int ks = 0; ks < 4; ks++) {
            uint32_t af[4][4], bf[2][4];
#pragma unroll
            for (int mi = 0; mi < 4; mi++)
                ldsm4(af[mi], As + swz((uint32_t)(a_row[mi] * 128 + ks * 32 + a_koff)));
#pragma unroll
            for (int n2 = 0; n2 < 2; n2++)
                ldsm4(bf[n2], Bs + swz((uint32_t)(b_row[n2] * 128 + ks * 32 + b_koff)));
#pragma unroll
            for (int mi = 0; mi < 4; mi++) {
#pragma unroll
                for (int ni = 0; ni < 4; ni++) {
                    uint32_t bb[2] = { bf[ni >> 1][(ni & 1) * 2], bf[ni >> 1][(ni & 1) * 2 + 1] };
                    mma_f16(acc[mi][ni], af[mi], bb);
                }
            }
        }
        __syncthreads();
    }

    const int er = lane >> 2;
    const int ec = (lane & 3) * 2;

    if (MODE == 0) {
#pragma unroll
        for (int mi = 0; mi < 4; mi++) {
            int row0 = bm + wm * 64 + mi * 16 + er;
#pragma unroll
            for (int ni = 0; ni < 4; ni++) {
                int col = bn + wn * 32 + ni * 8 + ec;
                *(float2*)(C + (size_t)row0 * ldc + col) = make_float2(acc[mi][ni][0], acc[mi][ni][1]);
                *(float2*)(C + (size_t)(row0 + 8) * ldc + col) = make_float2(acc[mi][ni][2], acc[mi][ni][3]);
            }
        }
    } else {
        // ---- QKV epilogue: stage 128x128 fp32 tile, RoPE + fp16 split ----
        float* sC = (float*)dsm;
        const int bx = blockIdx.x;                    // 0..23
        const int region = (bx < 16) ? 0 : (bx < 20 ? 1 : 2);   // Q / K / V
        const float sscale = 0.08838834764831845f;
        __syncthreads();
#pragma unroll
        for (int mi = 0; mi < 4; mi++) {
            int rr = wm * 64 + mi * 16 + er;
#pragma unroll
            for (int ni = 0; ni < 4; ni++) {
                int col = wn * 32 + ni * 8 + ec;
                sC[rr * SCW + col] = acc[mi][ni][0];
                sC[rr * SCW + col + 1] = acc[mi][ni][1];
                sC[(rr + 8) * SCW + col] = acc[mi][ni][2];
                sC[(rr + 8) * SCW + col + 1] = acc[mi][ni][3];
            }
        }
        __syncthreads();
#pragma unroll 4
        for (int it = 0; it < 32; it++) {
            int idx = tid + it * 256;                 // 8192 pairs
            int r = idx >> 6;
            int j = idx & 63;
            float x0 = sC[r * SCW + j];
            float x1 = sC[r * SCW + j + 64];
            int s = bm + r;
            if (region == 0) {
                float freq = powf(10000.0f, -(float)(2 * j) / (float)HD);
                float sn, cs;
                sincosf((float)s * freq, &sn, &cs);
                float y0 = (x0 * cs - x1 * sn) * sscale;
                float y1 = (x1 * cs + x0 * sn) * sscale;
                g_Qh[(size_t)s * HID + bn + j] = __float2half(y0);
                g_Qh[(size_t)s * HID + bn + j + 64] = __float2half(y1);
            } else if (region == 1) {
                float freq = powf(10000.0f, -(float)(2 * j) / (float)HD);
                float sn, cs;
                sincosf((float)s * freq, &sn, &cs);
                float y0 = x0 * cs - x1 * sn;
                float y1 = x1 * cs + x0 * sn;
                int kc = bn - HID + j;
                __half h0 = __float2half(y0), h1 = __float2half(y1);
                g_Khi[(size_t)s * KVDIM + kc] = h0;
                g_Khi[(size_t)s * KVDIM + kc + 64] = h1;
                g_Klo[(size_t)s * KVDIM + kc] = __float2half(y0 - __half2float(h0));
                g_Klo[(size_t)s * KVDIM + kc + 64] = __float2half(y1 - __half2float(h1));
            } else {
                int vc = bn - HID - KVDIM + j;
                __half h0 = __float2half(x0), h1 = __float2half(x1);
                g_Vhi[(size_t)s * KVDIM + vc] = h0;
                g_Vhi[(size_t)s * KVDIM + vc + 64] = h1;
                g_Vlo[(size_t)s * KVDIM + vc] = __float2half(x0 - __half2float(h0));
                g_Vlo[(size_t)s * KVDIM + vc + 64] = __float2half(x1 - __half2float(h1));
            }
        }
    }
}

// ---------------------------------------------------------------------------
// HMMA flash attention (causal, GQA), fp16 2-term (proven, unchanged).
// CTA = 128 threads (4 warps), 64 q-rows; KV tile 32, double-buffered. 80KB.
// ---------------------------------------------------------------------------
#define Q_OFF 0
#define KVB_OFF(b) (16384 + (b) * 32768)
#define KHI_O 0
#define KLO_O 8192
#define VHI_O 16384
#define VLO_O 24576
#define FLASH_SMEM 81920

__global__ __launch_bounds__(128)
void flash_mma(const __half* __restrict__ Qp,
               const __half* __restrict__ Kh, const __half* __restrict__ Kl,
               const __half* __restrict__ Vh, const __half* __restrict__ Vl,
               __half* __restrict__ attn_out) {
    extern __shared__ char dsm[];
    const uint32_t base = smem_u32(dsm);
    const int tid  = threadIdx.x;
    const int lane = tid & 31;
    const int warp = tid >> 5;
    const int qt   = (int)gridDim.x - 1 - (int)blockIdx.x;
    const int h    = blockIdx.y;
    const int kvh  = h >> 2;
    const int wrow = warp * 16;
    const int nt   = 2 * qt + 2;
    const int q_row0 = qt * 64;

    const int rr = tid >> 4;
    const int cc = (tid & 15) * 8;
    const int panel = cc >> 6;
    const int col = cc & 63;

    {
        const __half* qg = Qp + (size_t)q_row0 * HID + h * HD + cc;
#pragma unroll
        for (int i = 0; i < 8; i++) {
            int r = rr + i * 8;
            uint32_t d = panel * 8192 + swz((uint32_t)(r * 128 + col * 2));
            cpasync16(base + Q_OFF + d, qg + (size_t)r * HID);
        }
    }
    auto issue_kv = [&](int kb, int buf) {
        const uint32_t kvb = base + KVB_OFF(buf);
#pragma unroll
        for (int i = 0; i < 4; i++) {
            int r = rr + i * 8;
            uint32_t d = panel * 4096 + swz((uint32_t)(r * 128 + col * 2));
            size_t g = (size_t)(kb * 32 + r) * KVDIM + kvh * HD + cc;
            cpasync16(kvb + KHI_O + d, Kh + g);
            cpasync16(kvb + KLO_O + d, Kl + g);
            cpasync16(kvb + VHI_O + d, Vh + g);
            cpasync16(kvb + VLO_O + d, Vl + g);
        }
        asm volatile("cp.async.commit_group;" ::: "memory");
    };
    issue_kv(0, 0);
    asm volatile("cp.async.wait_group 0;" ::: "memory");
    __syncthreads();

    auto ldQ = [&](int ks, uint32_t* a) {
        int row = wrow + (lane & 15);
        int kc = (16 * ks) & 63;
        uint32_t addr = base + Q_OFF + (ks >> 2) * 8192 +
                        swz((uint32_t)(row * 128 + (kc + (lane >> 4) * 8) * 2));
        ldsm4(a, addr);
    };
    auto ldK = [&](uint32_t arr, int ks, int nb, uint32_t* b) {
        int row = nb * 16 + (lane & 7) + ((lane >> 4) << 3);
        int kc = (16 * ks) & 63;
        int kadd = ((lane >> 3) & 1) * 8;
        uint32_t addr = base + arr + (ks >> 2) * 4096 +
                        swz((uint32_t)(row * 128 + (kc + kadd) * 2));
        ldsm4(b, addr);
    };
    auto ldV = [&](uint32_t arr, int ks, int db, uint32_t* b) {
        int row = ks * 16 + (lane & 7) + (((lane >> 3) & 1) << 3);
        int dc = (16 * db) & 63;
        int dadd = (lane >> 4) * 8;
        uint32_t addr = base + arr + (db >> 2) * 4096 +
                        swz((uint32_t)(row * 128 + (dc + dadd) * 2));
        ldsm4t(b, addr);
    };

    float oacc[16][4];
#pragma unroll
    for (int i = 0; i < 16; i++)
#pragma unroll
        for (int v = 0; v < 4; v++) oacc[i][v] = 0.f;
    float ml[2] = {-1e30f, -1e30f};
    float ll[2] = {0.f, 0.f};

    for (int kb = 0; kb < nt; kb++) {
        const int buf = kb & 1;
        if (kb + 1 < nt) {
            issue_kv(kb + 1, buf ^ 1);
            asm volatile("cp.async.wait_group 1;" ::: "memory");
        } else {
            asm volatile("cp.async.wait_group 0;" ::: "memory");
        }
        __syncthreads();

        const uint32_t kvb = KVB_OFF(buf);

        float pacc[4][4];
#pragma unroll
        for (int i = 0; i < 4; i++)
#pragma unroll
            for (int v = 0; v < 4; v++) pacc[i][v] = 0.f;

#pragma unroll
        for (int ks = 0; ks < 8; ks++) {
            uint32_t aq[4];
            ldQ(ks, aq);
#pragma unroll
            for (int nb = 0; nb < 2; nb++) {
                uint32_t bh[4], bl[4];
                ldK(kvb + KHI_O, ks, nb, bh);
                ldK(kvb + KLO_O, ks, nb, bl);
                mma_f16(pacc[2 * nb],     aq, bh);
                mma_f16(pacc[2 * nb + 1], aq, bh + 2);
                mma_f16(pacc[2 * nb],     aq, bl);
                mma_f16(pacc[2 * nb + 1], aq, bl + 2);
            }
        }

        if (kb >= 2 * qt) {
            int r0 = q_row0 + wrow + (lane >> 2);
#pragma unroll
            for (int ni = 0; ni < 4; ni++) {
                int c0 = kb * 32 + ni * 8 + (lane & 3) * 2;
                if (c0     > r0)     pacc[ni][0] = -1e30f;
                if (c0 + 1 > r0)     pacc[ni][1] = -1e30f;
                if (c0     > r0 + 8) pacc[ni][2] = -1e30f;
                if (c0 + 1 > r0 + 8) pacc[ni][3] = -1e30f;
            }
        }

        float mx0 = -1e30f, mx1 = -1e30f;
#pragma unroll
        for (int ni = 0; ni < 4; ni++) {
            mx0 = fmaxf(mx0, fmaxf(pacc[ni][0], pacc[ni][1]));
            mx1 = fmaxf(mx1, fmaxf(pacc[ni][2], pacc[ni][3]));
        }
        mx0 = fmaxf(mx0, __shfl_xor_sync(0xffffffffu, mx0, 1));
        mx0 = fmaxf(mx0, __shfl_xor_sync(0xffffffffu, mx0, 2));
        mx1 = fmaxf(mx1, __shfl_xor_sync(0xffffffffu, mx1, 1));
        mx1 = fmaxf(mx1, __shfl_xor_sync(0xffffffffu, mx1, 2));
        float mn0 = fmaxf(ml[0], mx0);
        float mn1 = fmaxf(ml[1], mx1);
        float sc0 = __expf(ml[0] - mn0);
        float sc1 = __expf(ml[1] - mn1);

        uint32_t phi[8];
        float ps0 = 0.f, ps1 = 0.f;
#pragma unroll
        for (int ni = 0; ni < 4; ni++) {
            float p0 = __expf(pacc[ni][0] - mn0);
            float p1 = __expf(pacc[ni][1] - mn0);
            float p2 = __expf(pacc[ni][2] - mn1);
            float p3 = __expf(pacc[ni][3] - mn1);
            ps0 += p0 + p1;
            ps1 += p2 + p3;
            phi[2 * ni]     = pack_h2(p0, p1);
            phi[2 * ni + 1] = pack_h2(p2, p3);
        }
        ps0 += __shfl_xor_sync(0xffffffffu, ps0, 1);
        ps0 += __shfl_xor_sync(0xffffffffu, ps0, 2);
        ps1 += __shfl_xor_sync(0xffffffffu, ps1, 1);
        ps1 += __shfl_xor_sync(0xffffffffu, ps1, 2);
        ll[0] = ll[0] * sc0 + ps0;
        ll[1] = ll[1] * sc1 + ps1;
        ml[0] = mn0; ml[1] = mn1;
#pragma unroll
        for (int ni = 0; ni < 16; ni++) {
            oacc[ni][0] *= sc0; oacc[ni][1] *= sc0;
            oacc[ni][2] *= sc1; oacc[ni][3] *= sc1;
        }

#pragma unroll
        for (int ks = 0; ks < 2; ks++) {
            uint32_t aph[4] = { phi[4 * ks], phi[4 * ks + 1], phi[4 * ks + 2], phi[4 * ks + 3] };
#pragma unroll
            for (int db = 0; db < 8; db++) {
                uint32_t bh[4], bl[4];
                ldV(kvb + VHI_O, ks, db, bh);
                mma_f16(oacc[2 * db],     aph, bh);
                mma_f16(oacc[2 * db + 1], aph, bh + 2);
                ldV(kvb + VLO_O, ks, db, bl);
                mma_f16(oacc[2 * db],     aph, bl);
                mma_f16(oacc[2 * db + 1], aph, bl + 2);
            }
        }
        __syncthreads();
    }

    float inv0 = 1.0f / ll[0];
    float inv1 = 1.0f / ll[1];
    int row0 = q_row0 + wrow + (lane >> 2);
#pragma unroll
    for (int ni = 0; ni < 16; ni++) {
        int col = h * HD + ni * 8 + (lane & 3) * 2;
        __half2 v0 = __floats2half2_rn(oacc[ni][0] * inv0, oacc[ni][1] * inv0);
        __half2 v1 = __floats2half2_rn(oacc[ni][2] * inv1, oacc[ni][3] * inv1);
        *(__half2*)(attn_out + (size_t)row0 * HID + col) = v0;
        *(__half2*)(attn_out + (size_t)(row0 + 8) * HID + col) = v1;
    }
}

// ---------------------------------------------------------------------------
extern "C" void kernel_launch(void* const* d_in, const int* in_sizes, int n_in,
                              void* d_out, int out_size) {
    const float* X  = (const float*)d_in[0];
    const float* Wq = (const float*)d_in[1];
    const float* Wk = (const float*)d_in[2];
    const float* Wv = (const float*)d_in[3];
    const float* Wo = (const float*)d_in[4];
    float* out = (float*)d_out;

    void* p;
    cudaGetSymbolAddress(&p, g_attnh);  __half* attnh = (__half*)p;
    cudaGetSymbolAddress(&p, g_Xh);     __half* Xh    = (__half*)p;
    cudaGetSymbolAddress(&p, g_Wqkvh);  __half* Wqkvh = (__half*)p;
    cudaGetSymbolAddress(&p, g_Woh);    __half* Woh   = (__half*)p;
    __half *Qh, *Kh, *Kl, *Vh, *Vl;
    cudaGetSymbolAddress(&p, g_Qh);  Qh = (__half*)p;
    cudaGetSymbolAddress(&p, g_Khi); Kh = (__half*)p;
    cudaGetSymbolAddress(&p, g_Klo); Kl = (__half*)p;
    cudaGetSymbolAddress(&p, g_Vhi); Vh = (__half*)p;
    cudaGetSymbolAddress(&p, g_Vlo); Vl = (__half*)p;

    cudaFuncSetAttribute(gemm_mma<0>, cudaFuncAttributeMaxDynamicSharedMemorySize, GEMM_SMEM);
    cudaFuncSetAttribute(gemm_mma<1>, cudaFuncAttributeMaxDynamicSharedMemorySize, GEMM_SMEM);
    cudaFuncSetAttribute(flash_mma, cudaFuncAttributeMaxDynamicSharedMemorySize, FLASH_SMEM);

    // all conversions in one launch (plain fp16 everywhere)
    convert_all<<<(CONV_N4 + 255) / 256, 256>>>(
        (const float4*)Wq, (const float4*)Wk, (const float4*)Wv,
        (const float4*)Wo, (const float4*)X);

    // QKV projection: single-term weights + fused RoPE epilogue
    gemm_mma<1><<<dim3(QKVW / 128, S_LEN / 128), 256, GEMM_SMEM>>>(Xh, Wqkvh, nullptr, 0);

    // HMMA causal flash attention -> fp16
    flash_mma<<<dim3(S_LEN / 64, NH), 128, FLASH_SMEM>>>(Qh, Kh, Kl, Vh, Vl, attnh);

    // Output projection: single-term weights
    gemm_mma<0><<<dim3(HID / 128, S_LEN / 128), 256, GEMM_SMEM>>>(attnh, Woh, out, HID);
}

// round 16
// speedup vs baseline: 2.0995x; 1.3671x over previous
#include <cuda_runtime.h>
#include <cuda_fp16.h>
#include <math.h>
#include <stdint.h>

// Problem constants
#define S_LEN  2048
#define HID    2048
#define NH     16
#define NKV    4
#define HD     128
#define KVDIM  512
#define QKVW   3072
#define K0     2048

// Scratch (device globals — no allocation allowed)
__device__ __half g_attnh[S_LEN * HID];          // attention output (fp16, A-side)
__device__ __half g_Xh[S_LEN * K0];              // X rounded fp16
__device__ __half g_Wqkvh[QKVW * K0];            // Wq|Wk|Wv fp16 single-term
__device__ __half g_Woh[HID * K0];               // Wo fp16 single-term
// attention operands (all single fp16 now)
__device__ __half g_Qh[S_LEN * HID];             // scaled+rope q
__device__ __half g_Kh[S_LEN * KVDIM];           // rope'd k
__device__ __half g_Vh[S_LEN * KVDIM];           // v

// ---------------------------------------------------------------------------
// helpers
// ---------------------------------------------------------------------------
__device__ __forceinline__ uint32_t smem_u32(const void* p) {
    uint32_t a;
    asm("{ .reg .u64 t; cvta.to.shared.u64 t, %1; cvt.u32.u64 %0, t; }" : "=r"(a) : "l"(p));
    return a;
}
__device__ __forceinline__ void cpasync16(uint32_t s, const void* g) {
    asm volatile("cp.async.cg.shared.global [%0], [%1], 16;" :: "r"(s), "l"(g) : "memory");
}
__device__ __forceinline__ uint32_t swz(uint32_t off) {        // SW128 XOR swizzle
    return off ^ ((off >> 3) & 0x70);
}
__device__ __forceinline__ void ldsm4(uint32_t* r, uint32_t addr) {
    asm volatile("ldmatrix.sync.aligned.m8n8.x4.shared.b16 {%0,%1,%2,%3}, [%4];"
                 : "=r"(r[0]), "=r"(r[1]), "=r"(r[2]), "=r"(r[3]) : "r"(addr));
}
__device__ __forceinline__ void ldsm4t(uint32_t* r, uint32_t addr) {
    asm volatile("ldmatrix.sync.aligned.m8n8.x4.trans.shared.b16 {%0,%1,%2,%3}, [%4];"
                 : "=r"(r[0]), "=r"(r[1]), "=r"(r[2]), "=r"(r[3]) : "r"(addr));
}
__device__ __forceinline__ void mma_f16(float* d, const uint32_t* a, const uint32_t* b) {
    asm volatile(
        "mma.sync.aligned.m16n8k16.row.col.f32.f16.f16.f32 "
        "{%0,%1,%2,%3}, {%4,%5,%6,%7}, {%8,%9}, {%0,%1,%2,%3};"
        : "+f"(d[0]), "+f"(d[1]), "+f"(d[2]), "+f"(d[3])
        : "r"(a[0]), "r"(a[1]), "r"(a[2]), "r"(a[3]), "r"(b[0]), "r"(b[1]));
}
__device__ __forceinline__ uint32_t pack_h2(float lo, float hi) {
    __half2 t = __floats2half2_rn(lo, hi);
    return *reinterpret_cast<uint32_t*>(&t);
}

// ---------------------------------------------------------------------------
// Merged conversion kernel (row space: Wq|Wk|Wv|Wo|X, all plain fp16 round)
// ---------------------------------------------------------------------------
#define CONV_N4 ((QKVW + HID + S_LEN) * (K0 / 4))

__global__ void convert_all(const float4* __restrict__ Wq, const float4* __restrict__ Wk,
                            const float4* __restrict__ Wv, const float4* __restrict__ Wo,
                            const float4* __restrict__ X) {
    int idx = blockIdx.x * 256 + threadIdx.x;
    if (idx >= CONV_N4) return;
    int e = idx * 4;
    int r = e >> 11;
    int c = e & (K0 - 1);

    const float4* src;
    __half* dst;
    if (r < HID) {
        src = Wq + (((size_t)r * K0 + c) >> 2);
        dst = g_Wqkvh + (size_t)r * K0 + c;
    } else if (r < HID + KVDIM) {
        src = Wk + (((size_t)(r - HID) * K0 + c) >> 2);
        dst = g_Wqkvh + (size_t)r * K0 + c;
    } else if (r < QKVW) {
        src = Wv + (((size_t)(r - HID - KVDIM) * K0 + c) >> 2);
        dst = g_Wqkvh + (size_t)r * K0 + c;
    } else if (r < QKVW + HID) {
        src = Wo + (((size_t)(r - QKVW) * K0 + c) >> 2);
        dst = g_Woh + (size_t)(r - QKVW) * K0 + c;
    } else {
        int xr = r - (QKVW + HID);
        src = X + (((size_t)xr * K0 + c) >> 2);
        dst = g_Xh + (size_t)xr * K0 + c;
    }
    float4 v = *src;
    __half2* o = (__half2*)dst;
    o[0] = __floats2half2_rn(v.x, v.y);
    o[1] = __floats2half2_rn(v.z, v.w);
}

// ---------------------------------------------------------------------------
// fp16 HMMA GEMM (single-term): C[bm+128, bn+128] = A B^T over K0=2048.
// CTA 128x128, KB=64, 8 warps (2x4), warp tile 64x32, 3-stage, 2 CTAs/SM.
// MODE 0: store fp32 C.  MODE 1: fused RoPE + fp16 QKV epilogue.
// ---------------------------------------------------------------------------
#define KB      64
#define NKB     (K0 / KB)           // 32
#define STG     32768
#define GEMM_SMEM (3 * STG)         // 98304
#define SCW     132

template <int MODE>
__global__ __launch_bounds__(256)
void gemm_mma(const __half* __restrict__ A, const __half* __restrict__ B,
              float* __restrict__ C, int ldc) {
    extern __shared__ char dsm[];
    const uint32_t base = smem_u32(dsm);
    const int tid  = threadIdx.x;
    const int wid  = tid >> 5;
    const int lane = tid & 31;
    const int wm   = wid >> 2;
    const int wn   = wid & 3;
    const int quad = lane >> 3;
    const int l8   = lane & 7;
    const int bm = blockIdx.y * 128;
    const int bn = blockIdx.x * 128;

    const __half* Abase = A + (size_t)bm * K0;
    const __half* Bbase = B + (size_t)bn * K0;

    float acc[4][4][4];
#pragma unroll
    for (int i = 0; i < 4; i++)
#pragma unroll
        for (int j = 0; j < 4; j++)
#pragma unroll
            for (int v = 0; v < 4; v++) acc[i][j][v] = 0.f;

    int a_row[4], b_row[2];
#pragma unroll
    for (int mi = 0; mi < 4; mi++) a_row[mi] = wm * 64 + mi * 16 + (quad & 1) * 8 + l8;
#pragma unroll
    for (int n2 = 0; n2 < 2; n2++) b_row[n2] = wn * 32 + n2 * 16 + (quad >> 1) * 8 + l8;
    const int a_koff = (quad >> 1) * 16;
    const int b_koff = (quad & 1) * 16;

    const int ld_r = tid >> 3;
    const int ld_c = (tid & 7) * 8;

    auto issue_loads = [&](int kb, int buf) {
        const __half* ag = Abase + (size_t)ld_r * K0 + kb * KB + ld_c;
        const __half* bg = Bbase + (size_t)ld_r * K0 + kb * KB + ld_c;
        const uint32_t sa = base + buf * STG;
        const uint32_t sb = sa + 16384;
#pragma unroll
        for (int i = 0; i < 4; i++) {
            uint32_t s = swz((uint32_t)((ld_r + i * 32) * 128 + ld_c * 2));
            cpasync16(sa + s, ag + (size_t)i * 32 * K0);
            cpasync16(sb + s, bg + (size_t)i * 32 * K0);
        }
        asm volatile("cp.async.commit_group;" ::: "memory");
    };

    issue_loads(0, 0);
    issue_loads(1, 1);

    for (int kb = 0; kb < NKB; kb++) {
        const int buf = kb % 3;
        if (kb + 2 < NKB) {
            issue_loads(kb + 2, (kb + 2) % 3);
            asm volatile("cp.async.wait_group 2;" ::: "memory");
        } else if (kb + 1 < NKB) {
            asm volatile("cp.async.wait_group 1;" ::: "memory");
        } else {
            asm volatile("cp.async.wait_group 0;" ::: "memory");
        }
        __syncthreads();

        const uint32_t As = base + buf * STG;
        const uint32_t Bs = As + 16384;
#pragma unroll
        for (int ks = 0; ks < 4; ks++) {
            uint32_t af[4][4], bf[2][4];
#pragma unroll
            for (int mi = 0; mi < 4; mi++)
                ldsm4(af[mi], As + swz((uint32_t)(a_row[mi] * 128 + ks * 32 + a_koff)));
#pragma unroll
            for (int n2 = 0; n2 < 2; n2++)
                ldsm4(bf[n2], Bs + swz((uint32_t)(b_row[n2] * 128 + ks * 32 + b_koff)));
#pragma unroll
            for (int mi = 0; mi < 4; mi++) {
#pragma unroll
                for (int ni = 0; ni < 4; ni++) {
                    uint32_t bb[2] = { bf[ni >> 1][(ni & 1) * 2], bf[ni >> 1][(ni & 1) * 2 + 1] };
                    mma_f16(acc[mi][ni], af[mi], bb);
                }
            }
        }
        __syncthreads();
    }

    const int er = lane >> 2;
    const int ec = (lane & 3) * 2;

    if (MODE == 0) {
#pragma unroll
        for (int mi = 0; mi < 4; mi++) {
            int row0 = bm + wm * 64 + mi * 16 + er;
#pragma unroll
            for (int ni = 0; ni < 4; ni++) {
                int col = bn + wn * 32 + ni * 8 + ec;
                *(float2*)(C + (size_t)row0 * ldc + col) = make_float2(acc[mi][ni][0], acc[mi][ni][1]);
                *(float2*)(C + (size_t)(row0 + 8) * ldc + col) = make_float2(acc[mi][ni][2], acc[mi][ni][3]);
            }
        }
    } else {
        // ---- QKV epilogue: stage 128x128 fp32 tile, RoPE + fp16 round ----
        float* sC = (float*)dsm;
        const int bx = blockIdx.x;                    // 0..23
        const int region = (bx < 16) ? 0 : (bx < 20 ? 1 : 2);   // Q / K / V
        const float sscale = 0.08838834764831845f;
        __syncthreads();
#pragma unroll
        for (int mi = 0; mi < 4; mi++) {
            int rr = wm * 64 + mi * 16 + er;
#pragma unroll
            for (int ni = 0; ni < 4; ni++) {
                int col = wn * 32 + ni * 8 + ec;
                sC[rr * SCW + col] = acc[mi][ni][0];
                sC[rr * SCW + col + 1] = acc[mi][ni][1];
                sC[(rr + 8) * SCW + col] = acc[mi][ni][2];
                sC[(rr + 8) * SCW + col + 1] = acc[mi][ni][3];
            }
        }
        __syncthreads();
#pragma unroll 4
        for (int it = 0; it < 32; it++) {
            int idx = tid + it * 256;                 // 8192 pairs
            int r = idx >> 6;
            int j = idx & 63;
            float x0 = sC[r * SCW + j];
            float x1 = sC[r * SCW + j + 64];
            int s = bm + r;
            if (region == 0) {
                float freq = powf(10000.0f, -(float)(2 * j) / (float)HD);
                float sn, cs;
                sincosf((float)s * freq, &sn, &cs);
                float y0 = (x0 * cs - x1 * sn) * sscale;
                float y1 = (x1 * cs + x0 * sn) * sscale;
                g_Qh[(size_t)s * HID + bn + j] = __float2half(y0);
                g_Qh[(size_t)s * HID + bn + j + 64] = __float2half(y1);
            } else if (region == 1) {
                float freq = powf(10000.0f, -(float)(2 * j) / (float)HD);
                float sn, cs;
                sincosf((float)s * freq, &sn, &cs);
                float y0 = x0 * cs - x1 * sn;
                float y1 = x1 * cs + x0 * sn;
                int kc = bn - HID + j;
                g_Kh[(size_t)s * KVDIM + kc] = __float2half(y0);
                g_Kh[(size_t)s * KVDIM + kc + 64] = __float2half(y1);
            } else {
                int vc = bn - HID - KVDIM + j;
                g_Vh[(size_t)s * KVDIM + vc] = __float2half(x0);
                g_Vh[(size_t)s * KVDIM + vc + 64] = __float2half(x1);
            }
        }
    }
}

// ---------------------------------------------------------------------------
// HMMA flash attention (causal, GQA), single-fp16 K and V.
// CTA = 128 threads (4 warps), 64 q-rows; KV tile 32, double-buffered.
// smem = Q 16KB + 2 x (K 8KB + V 8KB) = 48KB -> 3 CTAs/SM.
// ---------------------------------------------------------------------------
#define Q_OFF 0
#define KVB_OFF(b) (16384 + (b) * 16384)
#define K_O 0
#define V_O 8192
#define FLASH_SMEM 49152

__global__ __launch_bounds__(128, 3)
void flash_mma(const __half* __restrict__ Qp,
               const __half* __restrict__ Kp, const __half* __restrict__ Vp,
               __half* __restrict__ attn_out) {
    extern __shared__ char dsm[];
    const uint32_t base = smem_u32(dsm);
    const int tid  = threadIdx.x;
    const int lane = tid & 31;
    const int warp = tid >> 5;
    const int qt   = (int)gridDim.x - 1 - (int)blockIdx.x;   // big tiles first
    const int h    = blockIdx.y;
    const int kvh  = h >> 2;
    const int wrow = warp * 16;
    const int nt   = 2 * qt + 2;
    const int q_row0 = qt * 64;

    const int rr = tid >> 4;
    const int cc = (tid & 15) * 8;
    const int panel = cc >> 6;
    const int col = cc & 63;

    {
        const __half* qg = Qp + (size_t)q_row0 * HID + h * HD + cc;
#pragma unroll
        for (int i = 0; i < 8; i++) {
            int r = rr + i * 8;
            uint32_t d = panel * 8192 + swz((uint32_t)(r * 128 + col * 2));
            cpasync16(base + Q_OFF + d, qg + (size_t)r * HID);
        }
    }
    auto issue_kv = [&](int kb, int buf) {
        const uint32_t kvb = base + KVB_OFF(buf);
#pragma unroll
        for (int i = 0; i < 4; i++) {
            int r = rr + i * 8;
            uint32_t d = panel * 4096 + swz((uint32_t)(r * 128 + col * 2));
            size_t g = (size_t)(kb * 32 + r) * KVDIM + kvh * HD + cc;
            cpasync16(kvb + K_O + d, Kp + g);
            cpasync16(kvb + V_O + d, Vp + g);
        }
        asm volatile("cp.async.commit_group;" ::: "memory");
    };
    issue_kv(0, 0);
    asm volatile("cp.async.wait_group 0;" ::: "memory");
    __syncthreads();

    auto ldQ = [&](int ks, uint32_t* a) {
        int row = wrow + (lane & 15);
        int kc = (16 * ks) & 63;
        uint32_t addr = base + Q_OFF + (ks >> 2) * 8192 +
                        swz((uint32_t)(row * 128 + (kc + (lane >> 4) * 8) * 2));
        ldsm4(a, addr);
    };
    auto ldK = [&](uint32_t arr, int ks, int nb, uint32_t* b) {
        int row = nb * 16 + (lane & 7) + ((lane >> 4) << 3);
        int kc = (16 * ks) & 63;
        int kadd = ((lane >> 3) & 1) * 8;
        uint32_t addr = base + arr + (ks >> 2) * 4096 +
                        swz((uint32_t)(row * 128 + (kc + kadd) * 2));
        ldsm4(b, addr);
    };
    auto ldV = [&](uint32_t arr, int ks, int db, uint32_t* b) {
        int row = ks * 16 + (lane & 7) + (((lane >> 3) & 1) << 3);
        int dc = (16 * db) & 63;
        int dadd = (lane >> 4) * 8;
        uint32_t addr = base + arr + (db >> 2) * 4096 +
                        swz((uint32_t)(row * 128 + (dc + dadd) * 2));
        ldsm4t(b, addr);
    };

    float oacc[16][4];
#pragma unroll
    for (int i = 0; i < 16; i++)
#pragma unroll
        for (int v = 0; v < 4; v++) oacc[i][v] = 0.f;
    float ml[2] = {-1e30f, -1e30f};
    float ll[2] = {0.f, 0.f};

    for (int kb = 0; kb < nt; kb++) {
        const int buf = kb & 1;
        if (kb + 1 < nt) {
            issue_kv(kb + 1, buf ^ 1);
            asm volatile("cp.async.wait_group 1;" ::: "memory");
        } else {
            asm volatile("cp.async.wait_group 0;" ::: "memory");
        }
        __syncthreads();

        const uint32_t kvb = KVB_OFF(buf);

        // ---- scores: Q·K over 32 kv rows ----
        float pacc[4][4];
#pragma unroll
        for (int i = 0; i < 4; i++)
#pragma unroll
            for (int v = 0; v < 4; v++) pacc[i][v] = 0.f;

#pragma unroll
        for (int ks = 0; ks < 8; ks++) {
            uint32_t aq[4];
            ldQ(ks, aq);
#pragma unroll
            for (int nb = 0; nb < 2; nb++) {
                uint32_t bh[4];
                ldK(kvb + K_O, ks, nb, bh);
                mma_f16(pacc[2 * nb],     aq, bh);
                mma_f16(pacc[2 * nb + 1], aq, bh + 2);
            }
        }

        // ---- causal mask (diagonal tiles only) ----
        if (kb >= 2 * qt) {
            int r0 = q_row0 + wrow + (lane >> 2);
#pragma unroll
            for (int ni = 0; ni < 4; ni++) {
                int c0 = kb * 32 + ni * 8 + (lane & 3) * 2;
                if (c0     > r0)     pacc[ni][0] = -1e30f;
                if (c0 + 1 > r0)     pacc[ni][1] = -1e30f;
                if (c0     > r0 + 8) pacc[ni][2] = -1e30f;
                if (c0 + 1 > r0 + 8) pacc[ni][3] = -1e30f;
            }
        }

        // ---- online softmax ----
        float mx0 = -1e30f, mx1 = -1e30f;
#pragma unroll
        for (int ni = 0; ni < 4; ni++) {
            mx0 = fmaxf(mx0, fmaxf(pacc[ni][0], pacc[ni][1]));
            mx1 = fmaxf(mx1, fmaxf(pacc[ni][2], pacc[ni][3]));
        }
        mx0 = fmaxf(mx0, __shfl_xor_sync(0xffffffffu, mx0, 1));
        mx0 = fmaxf(mx0, __shfl_xor_sync(0xffffffffu, mx0, 2));
        mx1 = fmaxf(mx1, __shfl_xor_sync(0xffffffffu, mx1, 1));
        mx1 = fmaxf(mx1, __shfl_xor_sync(0xffffffffu, mx1, 2));
        float mn0 = fmaxf(ml[0], mx0);
        float mn1 = fmaxf(ml[1], mx1);
        float sc0 = __expf(ml[0] - mn0);
        float sc1 = __expf(ml[1] - mn1);

        uint32_t phi[8];
        float ps0 = 0.f, ps1 = 0.f;
#pragma unroll
        for (int ni = 0; ni < 4; ni++) {
            float p0 = __expf(pacc[ni][0] - mn0);
            float p1 = __expf(pacc[ni][1] - mn0);
            float p2 = __expf(pacc[ni][2] - mn1);
            float p3 = __expf(pacc[ni][3] - mn1);
            ps0 += p0 + p1;
            ps1 += p2 + p3;
            phi[2 * ni]     = pack_h2(p0, p1);
            phi[2 * ni + 1] = pack_h2(p2, p3);
        }
        ps0 += __shfl_xor_sync(0xffffffffu, ps0, 1);
        ps0 += __shfl_xor_sync(0xffffffffu, ps0, 2);
        ps1 += __shfl_xor_sync(0xffffffffu, ps1, 1);
        ps1 += __shfl_xor_sync(0xffffffffu, ps1, 2);
        ll[0] = ll[0] * sc0 + ps0;
        ll[1] = ll[1] * sc1 + ps1;
        ml[0] = mn0; ml[1] = mn1;
#pragma unroll
        for (int ni = 0; ni < 16; ni++) {
            oacc[ni][0] *= sc0; oacc[ni][1] *= sc0;
            oacc[ni][2] *= sc1; oacc[ni][3] *= sc1;
        }

        // ---- O += P·V ----
#pragma unroll
        for (int ks = 0; ks < 2; ks++) {
            uint32_t aph[4] = { phi[4 * ks], phi[4 * ks + 1], phi[4 * ks + 2], phi[4 * ks + 3] };
#pragma unroll
            for (int db = 0; db < 8; db++) {
                uint32_t bh[4];
                ldV(kvb + V_O, ks, db, bh);
                mma_f16(oacc[2 * db],     aph, bh);
                mma_f16(oacc[2 * db + 1], aph, bh + 2);
            }
        }
        __syncthreads();
    }

    // ---- epilogue: write fp16 ----
    float inv0 = 1.0f / ll[0];
    float inv1 = 1.0f / ll[1];
    int row0 = q_row0 + wrow + (lane >> 2);
#pragma unroll
    for (int ni = 0; ni < 16; ni++) {
        int col = h * HD + ni * 8 + (lane & 3) * 2;
        __half2 v0 = __floats2half2_rn(oacc[ni][0] * inv0, oacc[ni][1] * inv0);
        __half2 v1 = __floats2half2_rn(oacc[ni][2] * inv1, oacc[ni][3] * inv1);
        *(__half2*)(attn_out + (size_t)row0 * HID + col) = v0;
        *(__half2*)(attn_out + (size_t)(row0 + 8) * HID + col) = v1;
    }
}

// ---------------------------------------------------------------------------
extern "C" void kernel_launch(void* const* d_in, const int* in_sizes, int n_in,
                              void* d_out, int out_size) {
    const float* X  = (const float*)d_in[0];
    const float* Wq = (const float*)d_in[1];
    const float* Wk = (const float*)d_in[2];
    const float* Wv = (const float*)d_in[3];
    const float* Wo = (const float*)d_in[4];
    float* out = (float*)d_out;

    void* p;
    cudaGetSymbolAddress(&p, g_attnh);  __half* attnh = (__half*)p;
    cudaGetSymbolAddress(&p, g_Xh);     __half* Xh    = (__half*)p;
    cudaGetSymbolAddress(&p, g_Wqkvh);  __half* Wqkvh = (__half*)p;
    cudaGetSymbolAddress(&p, g_Woh);    __half* Woh   = (__half*)p;
    __half *Qh, *Kh, *Vh;
    cudaGetSymbolAddress(&p, g_Qh); Qh = (__half*)p;
    cudaGetSymbolAddress(&p, g_Kh); Kh = (__half*)p;
    cudaGetSymbolAddress(&p, g_Vh); Vh = (__half*)p;

    cudaFuncSetAttribute(gemm_mma<0>, cudaFuncAttributeMaxDynamicSharedMemorySize, GEMM_SMEM);
    cudaFuncSetAttribute(gemm_mma<1>, cudaFuncAttributeMaxDynamicSharedMemorySize, GEMM_SMEM);
    cudaFuncSetAttribute(flash_mma, cudaFuncAttributeMaxDynamicSharedMemorySize, FLASH_SMEM);

    // all conversions in one launch
    convert_all<<<(CONV_N4 + 255) / 256, 256>>>(
        (const float4*)Wq, (const float4*)Wk, (const float4*)Wv,
        (const float4*)Wo, (const float4*)X);

    // QKV projection: single-term weights + fused RoPE epilogue
    gemm_mma<1><<<dim3(QKVW / 128, S_LEN / 128), 256, GEMM_SMEM>>>(Xh, Wqkvh, nullptr, 0);

    // HMMA causal flash attention (single-fp16 K/V) -> fp16
    flash_mma<<<dim3(S_LEN / 64, NH), 128, FLASH_SMEM>>>(Qh, Kh, Vh, attnh);

    // Output projection: single-term weights
    gemm_mma<0><<<dim3(HID / 128, S_LEN / 128), 256, GEMM_SMEM>>>(attnh, Woh, out, HID);
}

// round 17
// speedup vs baseline: 2.1252x; 1.0123x over previous
#include <cuda_runtime.h>
#include <cuda_fp16.h>
#include <math.h>
#include <stdint.h>

// Problem constants
#define S_LEN  2048
#define HID    2048
#define NH     16
#define NKV    4
#define HD     128
#define KVDIM  512
#define QKVW   3072
#define K0     2048

// Scratch (device globals — no allocation allowed)
__device__ __half g_attnh[S_LEN * HID];          // attention output (fp16, A-side)
__device__ __half g_Xh[S_LEN * K0];              // X rounded fp16
__device__ __half g_Wqkvh[QKVW * K0];            // Wq|Wk|Wv fp16
__device__ __half g_Woh[HID * K0];               // Wo fp16
// attention operands (single fp16)
__device__ __half g_Qh[S_LEN * HID];             // scaled+rope q
__device__ __half g_Kh[S_LEN * KVDIM];           // rope'd k
__device__ __half g_Vh[S_LEN * KVDIM];           // v

// ---------------------------------------------------------------------------
// helpers
// ---------------------------------------------------------------------------
__device__ __forceinline__ uint32_t smem_u32(const void* p) {
    uint32_t a;
    asm("{ .reg .u64 t; cvta.to.shared.u64 t, %1; cvt.u32.u64 %0, t; }" : "=r"(a) : "l"(p));
    return a;
}
__device__ __forceinline__ void cpasync16(uint32_t s, const void* g) {
    asm volatile("cp.async.cg.shared.global [%0], [%1], 16;" :: "r"(s), "l"(g) : "memory");
}
__device__ __forceinline__ uint32_t swz(uint32_t off) {        // SW128 XOR swizzle
    return off ^ ((off >> 3) & 0x70);
}
__device__ __forceinline__ void ldsm4(uint32_t* r, uint32_t addr) {
    asm volatile("ldmatrix.sync.aligned.m8n8.x4.shared.b16 {%0,%1,%2,%3}, [%4];"
                 : "=r"(r[0]), "=r"(r[1]), "=r"(r[2]), "=r"(r[3]) : "r"(addr));
}
__device__ __forceinline__ void ldsm4t(uint32_t* r, uint32_t addr) {
    asm volatile("ldmatrix.sync.aligned.m8n8.x4.trans.shared.b16 {%0,%1,%2,%3}, [%4];"
                 : "=r"(r[0]), "=r"(r[1]), "=r"(r[2]), "=r"(r[3]) : "r"(addr));
}
__device__ __forceinline__ void mma_f16(float* d, const uint32_t* a, const uint32_t* b) {
    asm volatile(
        "mma.sync.aligned.m16n8k16.row.col.f32.f16.f16.f32 "
        "{%0,%1,%2,%3}, {%4,%5,%6,%7}, {%8,%9}, {%0,%1,%2,%3};"
        : "+f"(d[0]), "+f"(d[1]), "+f"(d[2]), "+f"(d[3])
        : "r"(a[0]), "r"(a[1]), "r"(a[2]), "r"(a[3]), "r"(b[0]), "r"(b[1]));
}
__device__ __forceinline__ uint32_t pack_h2(float lo, float hi) {
    __half2 t = __floats2half2_rn(lo, hi);
    return *reinterpret_cast<uint32_t*>(&t);
}

// ---------------------------------------------------------------------------
// Merged conversion kernel (row space: Wq|Wk|Wv|Wo|X, all plain fp16 round)
// ---------------------------------------------------------------------------
#define CONV_N4 ((QKVW + HID + S_LEN) * (K0 / 4))

__global__ void convert_all(const float4* __restrict__ Wq, const float4* __restrict__ Wk,
                            const float4* __restrict__ Wv, const float4* __restrict__ Wo,
                            const float4* __restrict__ X) {
    int idx = blockIdx.x * 256 + threadIdx.x;
    if (idx >= CONV_N4) return;
    int e = idx * 4;
    int r = e >> 11;
    int c = e & (K0 - 1);

    const float4* src;
    __half* dst;
    if (r < HID) {
        src = Wq + (((size_t)r * K0 + c) >> 2);
        dst = g_Wqkvh + (size_t)r * K0 + c;
    } else if (r < HID + KVDIM) {
        src = Wk + (((size_t)(r - HID) * K0 + c) >> 2);
        dst = g_Wqkvh + (size_t)r * K0 + c;
    } else if (r < QKVW) {
        src = Wv + (((size_t)(r - HID - KVDIM) * K0 + c) >> 2);
        dst = g_Wqkvh + (size_t)r * K0 + c;
    } else if (r < QKVW + HID) {
        src = Wo + (((size_t)(r - QKVW) * K0 + c) >> 2);
        dst = g_Woh + (size_t)(r - QKVW) * K0 + c;
    } else {
        int xr = r - (QKVW + HID);
        src = X + (((size_t)xr * K0 + c) >> 2);
        dst = g_Xh + (size_t)xr * K0 + c;
    }
    float4 v = *src;
    __half2* o = (__half2*)dst;
    o[0] = __floats2half2_rn(v.x, v.y);
    o[1] = __floats2half2_rn(v.z, v.w);
}

#define KB  64
#define NKB (K0 / KB)               // 32

// ---------------------------------------------------------------------------
// O-projection GEMM (proven 49us config): CTA 128x128, 256 thr, 8 warps
// (2x4), warp tile 64x32, 3-stage (32KB stages), 2 CTAs/SM.
// ---------------------------------------------------------------------------
#define STG      32768
#define GEMM_SMEM (3 * STG)         // 98304

__global__ __launch_bounds__(256)
void gemm_o(const __half* __restrict__ A, const __half* __restrict__ B,
            float* __restrict__ C, int ldc) {
    extern __shared__ char dsm[];
    const uint32_t base = smem_u32(dsm);
    const int tid  = threadIdx.x;
    const int wid  = tid >> 5;
    const int lane = tid & 31;
    const int wm   = wid >> 2;
    const int wn   = wid & 3;
    const int quad = lane >> 3;
    const int l8   = lane & 7;
    const int bm = blockIdx.y * 128;
    const int bn = blockIdx.x * 128;

    const __half* Abase = A + (size_t)bm * K0;
    const __half* Bbase = B + (size_t)bn * K0;

    float acc[4][4][4];
#pragma unroll
    for (int i = 0; i < 4; i++)
#pragma unroll
        for (int j = 0; j < 4; j++)
#pragma unroll
            for (int v = 0; v < 4; v++) acc[i][j][v] = 0.f;

    int a_row[4], b_row[2];
#pragma unroll
    for (int mi = 0; mi < 4; mi++) a_row[mi] = wm * 64 + mi * 16 + (quad & 1) * 8 + l8;
#pragma unroll
    for (int n2 = 0; n2 < 2; n2++) b_row[n2] = wn * 32 + n2 * 16 + (quad >> 1) * 8 + l8;
    const int a_koff = (quad >> 1) * 16;
    const int b_koff = (quad & 1) * 16;

    const int ld_r = tid >> 3;
    const int ld_c = (tid & 7) * 8;

    auto issue_loads = [&](int kb, int buf) {
        const __half* ag = Abase + (size_t)ld_r * K0 + kb * KB + ld_c;
        const __half* bg = Bbase + (size_t)ld_r * K0 + kb * KB + ld_c;
        const uint32_t sa = base + buf * STG;
        const uint32_t sb = sa + 16384;
#pragma unroll
        for (int i = 0; i < 4; i++) {
            uint32_t s = swz((uint32_t)((ld_r + i * 32) * 128 + ld_c * 2));
            cpasync16(sa + s, ag + (size_t)i * 32 * K0);
            cpasync16(sb + s, bg + (size_t)i * 32 * K0);
        }
        asm volatile("cp.async.commit_group;" ::: "memory");
    };

    issue_loads(0, 0);
    issue_loads(1, 1);

    for (int kb = 0; kb < NKB; kb++) {
        const int buf = kb % 3;
        if (kb + 2 < NKB) {
            issue_loads(kb + 2, (kb + 2) % 3);
            asm volatile("cp.async.wait_group 2;" ::: "memory");
        } else if (kb + 1 < NKB) {
            asm volatile("cp.async.wait_group 1;" ::: "memory");
        } else {
            asm volatile("cp.async.wait_group 0;" ::: "memory");
        }
        __syncthreads();

        const uint32_t As = base + buf * STG;
        const uint32_t Bs = As + 16384;
#pragma unroll
        for (int ks = 0; ks < 4; ks++) {
            uint32_t af[4][4], bf[2][4];
#pragma unroll
            for (int mi = 0; mi < 4; mi++)
                ldsm4(af[mi], As + swz((uint32_t)(a_row[mi] * 128 + ks * 32 + a_koff)));
#pragma unroll
            for (int n2 = 0; n2 < 2; n2++)
                ldsm4(bf[n2], Bs + swz((uint32_t)(b_row[n2] * 128 + ks * 32 + b_koff)));
#pragma unroll
            for (int mi = 0; mi < 4; mi++) {
#pragma unroll
                for (int ni = 0; ni < 4; ni++) {
                    uint32_t bb[2] = { bf[ni >> 1][(ni & 1) * 2], bf[ni >> 1][(ni & 1) * 2 + 1] };
                    mma_f16(acc[mi][ni], af[mi], bb);
                }
            }
        }
        __syncthreads();
    }

    const int er = lane >> 2;
    const int ec = (lane & 3) * 2;
#pragma unroll
    for (int mi = 0; mi < 4; mi++) {
        int row0 = bm + wm * 64 + mi * 16 + er;
#pragma unroll
        for (int ni = 0; ni < 4; ni++) {
            int col = bn + wn * 32 + ni * 8 + ec;
            *(float2*)(C + (size_t)row0 * ldc + col) = make_float2(acc[mi][ni][0], acc[mi][ni][1]);
            *(float2*)(C + (size_t)(row0 + 8) * ldc + col) = make_float2(acc[mi][ni][2], acc[mi][ni][3]);
        }
    }
}

// ---------------------------------------------------------------------------
// QKV GEMM: CTA 64x128, 128 thr, 4 warps (2x2), warp tile 32x64, 3-stage
// (24KB stages -> 72KB) => 3 CTAs/SM. Fused RoPE + fp16 epilogue.
// K-loop order identical to previous kernel (bit-identical results).
// ---------------------------------------------------------------------------
#define QSTG  24576
#define QKV_SMEM (3 * QSTG)         // 73728
#define SCW   132

__global__ __launch_bounds__(128, 3)
void gemm_qkv(const __half* __restrict__ A, const __half* __restrict__ B) {
    extern __shared__ char dsm[];
    const uint32_t base = smem_u32(dsm);
    const int tid  = threadIdx.x;
    const int wid  = tid >> 5;           // 0..3
    const int lane = tid & 31;
    const int wm   = wid >> 1;           // 0..1 (32-row group)
    const int wn   = wid & 1;            // 0..1 (64-col group)
    const int quad = lane >> 3;
    const int l8   = lane & 7;
    const int bm = blockIdx.y * 64;
    const int bn = blockIdx.x * 128;

    const __half* Abase = A + (size_t)bm * K0;
    const __half* Bbase = B + (size_t)bn * K0;

    float acc[2][8][4];
#pragma unroll
    for (int i = 0; i < 2; i++)
#pragma unroll
        for (int j = 0; j < 8; j++)
#pragma unroll
            for (int v = 0; v < 4; v++) acc[i][j][v] = 0.f;

    int a_row[2], b_row[4];
#pragma unroll
    for (int mi = 0; mi < 2; mi++) a_row[mi] = wm * 32 + mi * 16 + (quad & 1) * 8 + l8;
#pragma unroll
    for (int n2 = 0; n2 < 4; n2++) b_row[n2] = wn * 64 + n2 * 16 + (quad >> 1) * 8 + l8;
    const int a_koff = (quad >> 1) * 16;
    const int b_koff = (quad & 1) * 16;

    const int ld_r = tid >> 3;           // 0..15
    const int ld_c = (tid & 7) * 8;

    auto issue_loads = [&](int kb, int buf) {
        const __half* ag = Abase + (size_t)ld_r * K0 + kb * KB + ld_c;
        const __half* bg = Bbase + (size_t)ld_r * K0 + kb * KB + ld_c;
        const uint32_t sa = base + buf * QSTG;
        const uint32_t sb = sa + 8192;
#pragma unroll
        for (int i = 0; i < 4; i++) {    // A: 64 rows
            uint32_t s = swz((uint32_t)((ld_r + i * 16) * 128 + ld_c * 2));
            cpasync16(sa + s, ag + (size_t)i * 16 * K0);
        }
#pragma unroll
        for (int i = 0; i < 8; i++) {    // B: 128 rows
            uint32_t s = swz((uint32_t)((ld_r + i * 16) * 128 + ld_c * 2));
            cpasync16(sb + s, bg + (size_t)i * 16 * K0);
        }
        asm volatile("cp.async.commit_group;" ::: "memory");
    };

    issue_loads(0, 0);
    issue_loads(1, 1);

    for (int kb = 0; kb < NKB; kb++) {
        const int buf = kb % 3;
        if (kb + 2 < NKB) {
            issue_loads(kb + 2, (kb + 2) % 3);
            asm volatile("cp.async.wait_group 2;" ::: "memory");
        } else if (kb + 1 < NKB) {
            asm volatile("cp.async.wait_group 1;" ::: "memory");
        } else {
            asm volatile("cp.async.wait_group 0;" ::: "memory");
        }
        __syncthreads();

        const uint32_t As = base + buf * QSTG;
        const uint32_t Bs = As + 8192;
#pragma unroll
        for (int ks = 0; ks < 4; ks++) {
            uint32_t af[2][4], bf[4][4];
#pragma unroll
            for (int mi = 0; mi < 2; mi++)
                ldsm4(af[mi], As + swz((uint32_t)(a_row[mi] * 128 + ks * 32 + a_koff)));
#pragma unroll
            for (int n2 = 0; n2 < 4; n2++)
                ldsm4(bf[n2], Bs + swz((uint32_t)(b_row[n2] * 128 + ks * 32 + b_koff)));
#pragma unroll
            for (int mi = 0; mi < 2; mi++) {
#pragma unroll
                for (int nj = 0; nj < 8; nj++) {
                    uint32_t bb[2] = { bf[nj >> 1][(nj & 1) * 2], bf[nj >> 1][(nj & 1) * 2 + 1] };
                    mma_f16(acc[mi][nj], af[mi], bb);
                }
            }
        }
        __syncthreads();
    }

    // ---- epilogue: stage 64x128 fp32 tile, RoPE + fp16 round ----
    const int er = lane >> 2;
    const int ec = (lane & 3) * 2;
    float* sC = (float*)dsm;
    const int bx = blockIdx.x;                    // 0..23
    const int region = (bx < 16) ? 0 : (bx < 20 ? 1 : 2);   // Q / K / V
    const float sscale = 0.08838834764831845f;
    __syncthreads();
#pragma unroll
    for (int mi = 0; mi < 2; mi++) {
        int rr = wm * 32 + mi * 16 + er;
#pragma unroll
        for (int nj = 0; nj < 8; nj++) {
            int col = wn * 64 + nj * 8 + ec;
            sC[rr * SCW + col] = acc[mi][nj][0];
            sC[rr * SCW + col + 1] = acc[mi][nj][1];
            sC[(rr + 8) * SCW + col] = acc[mi][nj][2];
            sC[(rr + 8) * SCW + col + 1] = acc[mi][nj][3];
        }
    }
    __syncthreads();
#pragma unroll 4
    for (int it = 0; it < 32; it++) {
        int idx = tid + it * 128;                 // 4096 pairs (64 rows x 64)
        int r = idx >> 6;
        int j = idx & 63;
        float x0 = sC[r * SCW + j];
        float x1 = sC[r * SCW + j + 64];
        int s = bm + r;
        if (region == 0) {
            float freq = powf(10000.0f, -(float)(2 * j) / (float)HD);
            float sn, cs;
            sincosf((float)s * freq, &sn, &cs);
            float y0 = (x0 * cs - x1 * sn) * sscale;
            float y1 = (x1 * cs + x0 * sn) * sscale;
            g_Qh[(size_t)s * HID + bn + j] = __float2half(y0);
            g_Qh[(size_t)s * HID + bn + j + 64] = __float2half(y1);
        } else if (region == 1) {
            float freq = powf(10000.0f, -(float)(2 * j) / (float)HD);
            float sn, cs;
            sincosf((float)s * freq, &sn, &cs);
            float y0 = x0 * cs - x1 * sn;
            float y1 = x1 * cs + x0 * sn;
            int kc = bn - HID + j;
            g_Kh[(size_t)s * KVDIM + kc] = __float2half(y0);
            g_Kh[(size_t)s * KVDIM + kc + 64] = __float2half(y1);
        } else {
            int vc = bn - HID - KVDIM + j;
            g_Vh[(size_t)s * KVDIM + vc] = __float2half(x0);
            g_Vh[(size_t)s * KVDIM + vc + 64] = __float2half(x1);
        }
    }
}

// ---------------------------------------------------------------------------
// HMMA flash attention (causal, GQA), single-fp16 K and V (proven, unchanged).
// CTA = 128 threads (4 warps), 64 q-rows; KV tile 32, double-buffered.
// smem = 48KB -> 3 CTAs/SM.
// ---------------------------------------------------------------------------
#define Q_OFF 0
#define KVB_OFF(b) (16384 + (b) * 16384)
#define K_O 0
#define V_O 8192
#define FLASH_SMEM 49152

__global__ __launch_bounds__(128, 3)
void flash_mma(const __half* __restrict__ Qp,
               const __half* __restrict__ Kp, const __half* __restrict__ Vp,
               __half* __restrict__ attn_out) {
    extern __shared__ char dsm[];
    const uint32_t base = smem_u32(dsm);
    const int tid  = threadIdx.x;
    const int lane = tid & 31;
    const int warp = tid >> 5;
    const int qt   = (int)gridDim.x - 1 - (int)blockIdx.x;   // big tiles first
    const int h    = blockIdx.y;
    const int kvh  = h >> 2;
    const int wrow = warp * 16;
    const int nt   = 2 * qt + 2;
    const int q_row0 = qt * 64;

    const int rr = tid >> 4;
    const int cc = (tid & 15) * 8;
    const int panel = cc >> 6;
    const int col = cc & 63;

    {
        const __half* qg = Qp + (size_t)q_row0 * HID + h * HD + cc;
#pragma unroll
        for (int i = 0; i < 8; i++) {
            int r = rr + i * 8;
            uint32_t d = panel * 8192 + swz((uint32_t)(r * 128 + col * 2));
            cpasync16(base + Q_OFF + d, qg + (size_t)r * HID);
        }
    }
    auto issue_kv = [&](int kb, int buf) {
        const uint32_t kvb = base + KVB_OFF(buf);
#pragma unroll
        for (int i = 0; i < 4; i++) {
            int r = rr + i * 8;
            uint32_t d = panel * 4096 + swz((uint32_t)(r * 128 + col * 2));
            size_t g = (size_t)(kb * 32 + r) * KVDIM + kvh * HD + cc;
            cpasync16(kvb + K_O + d, Kp + g);
            cpasync16(kvb + V_O + d, Vp + g);
        }
        asm volatile("cp.async.commit_group;" ::: "memory");
    };
    issue_kv(0, 0);
    asm volatile("cp.async.wait_group 0;" ::: "memory");
    __syncthreads();

    auto ldQ = [&](int ks, uint32_t* a) {
        int row = wrow + (lane & 15);
        int kc = (16 * ks) & 63;
        uint32_t addr = base + Q_OFF + (ks >> 2) * 8192 +
                        swz((uint32_t)(row * 128 + (kc + (lane >> 4) * 8) * 2));
        ldsm4(a, addr);
    };
    auto ldK = [&](uint32_t arr, int ks, int nb, uint32_t* b) {
        int row = nb * 16 + (lane & 7) + ((lane >> 4) << 3);
        int kc = (16 * ks) & 63;
        int kadd = ((lane >> 3) & 1) * 8;
        uint32_t addr = base + arr + (ks >> 2) * 4096 +
                        swz((uint32_t)(row * 128 + (kc + kadd) * 2));
        ldsm4(b, addr);
    };
    auto ldV = [&](uint32_t arr, int ks, int db, uint32_t* b) {
        int row = ks * 16 + (lane & 7) + (((lane >> 3) & 1) << 3);
        int dc = (16 * db) & 63;
        int dadd = (lane >> 4) * 8;
        uint32_t addr = base + arr + (db >> 2) * 4096 +
                        swz((uint32_t)(row * 128 + (dc + dadd) * 2));
        ldsm4t(b, addr);
    };

    float oacc[16][4];
#pragma unroll
    for (int i = 0; i < 16; i++)
#pragma unroll
        for (int v = 0; v < 4; v++) oacc[i][v] = 0.f;
    float ml[2] = {-1e30f, -1e30f};
    float ll[2] = {0.f, 0.f};

    for (int kb = 0; kb < nt; kb++) {
        const int buf = kb & 1;
        if (kb + 1 < nt) {
            issue_kv(kb + 1, buf ^ 1);
            asm volatile("cp.async.wait_group 1;" ::: "memory");
        } else {
            asm volatile("cp.async.wait_group 0;" ::: "memory");
        }
        __syncthreads();

        const uint32_t kvb = KVB_OFF(buf);

        float pacc[4][4];
#pragma unroll
        for (int i = 0; i < 4; i++)
#pragma unroll
            for (int v = 0; v < 4; v++) pacc[i][v] = 0.f;

#pragma unroll
        for (int ks = 0; ks < 8; ks++) {
            uint32_t aq[4];
            ldQ(ks, aq);
#pragma unroll
            for (int nb = 0; nb < 2; nb++) {
                uint32_t bh[4];
                ldK(kvb + K_O, ks, nb, bh);
                mma_f16(pacc[2 * nb],     aq, bh);
                mma_f16(pacc[2 * nb + 1], aq, bh + 2);
            }
        }

        if (kb >= 2 * qt) {
            int r0 = q_row0 + wrow + (lane >> 2);
#pragma unroll
            for (int ni = 0; ni < 4; ni++) {
                int c0 = kb * 32 + ni * 8 + (lane & 3) * 2;
                if (c0     > r0)     pacc[ni][0] = -1e30f;
                if (c0 + 1 > r0)     pacc[ni][1] = -1e30f;
                if (c0     > r0 + 8) pacc[ni][2] = -1e30f;
                if (c0 + 1 > r0 + 8) pacc[ni][3] = -1e30f;
            }
        }

        float mx0 = -1e30f, mx1 = -1e30f;
#pragma unroll
        for (int ni = 0; ni < 4; ni++) {
            mx0 = fmaxf(mx0, fmaxf(pacc[ni][0], pacc[ni][1]));
            mx1 = fmaxf(mx1, fmaxf(pacc[ni][2], pacc[ni][3]));
        }
        mx0 = fmaxf(mx0, __shfl_xor_sync(0xffffffffu, mx0, 1));
        mx0 = fmaxf(mx0, __shfl_xor_sync(0xffffffffu, mx0, 2));
        mx1 = fmaxf(mx1, __shfl_xor_sync(0xffffffffu, mx1, 1));
        mx1 = fmaxf(mx1, __shfl_xor_sync(0xffffffffu, mx1, 2));
        float mn0 = fmaxf(ml[0], mx0);
        float mn1 = fmaxf(ml[1], mx1);
        float sc0 = __expf(ml[0] - mn0);
        float sc1 = __expf(ml[1] - mn1);

        uint32_t phi[8];
        float ps0 = 0.f, ps1 = 0.f;
#pragma unroll
        for (int ni = 0; ni < 4; ni++) {
            float p0 = __expf(pacc[ni][0] - mn0);
            float p1 = __expf(pacc[ni][1] - mn0);
            float p2 = __expf(pacc[ni][2] - mn1);
            float p3 = __expf(pacc[ni][3] - mn1);
            ps0 += p0 + p1;
            ps1 += p2 + p3;
            phi[2 * ni]     = pack_h2(p0, p1);
            phi[2 * ni + 1] = pack_h2(p2, p3);
        }
        ps0 += __shfl_xor_sync(0xffffffffu, ps0, 1);
        ps0 += __shfl_xor_sync(0xffffffffu, ps0, 2);
        ps1 += __shfl_xor_sync(0xffffffffu, ps1, 1);
        ps1 += __shfl_xor_sync(0xffffffffu, ps1, 2);
        ll[0] = ll[0] * sc0 + ps0;
        ll[1] = ll[1] * sc1 + ps1;
        ml[0] = mn0; ml[1] = mn1;
#pragma unroll
        for (int ni = 0; ni < 16; ni++) {
            oacc[ni][0] *= sc0; oacc[ni][1] *= sc0;
            oacc[ni][2] *= sc1; oacc[ni][3] *= sc1;
        }

#pragma unroll
        for (int ks = 0; ks < 2; ks++) {
            uint32_t aph[4] = { phi[4 * ks], phi[4 * ks + 1], phi[4 * ks + 2], phi[4 * ks + 3] };
#pragma unroll
            for (int db = 0; db < 8; db++) {
                uint32_t bh[4];
                ldV(kvb + V_O, ks, db, bh);
                mma_f16(oacc[2 * db],     aph, bh);
                mma_f16(oacc[2 * db + 1], aph, bh + 2);
            }
        }
        __syncthreads();
    }

    float inv0 = 1.0f / ll[0];
    float inv1 = 1.0f / ll[1];
    int row0 = q_row0 + wrow + (lane >> 2);
#pragma unroll
    for (int ni = 0; ni < 16; ni++) {
        int col = h * HD + ni * 8 + (lane & 3) * 2;
        __half2 v0 = __floats2half2_rn(oacc[ni][0] * inv0, oacc[ni][1] * inv0);
        __half2 v1 = __floats2half2_rn(oacc[ni][2] * inv1, oacc[ni][3] * inv1);
        *(__half2*)(attn_out + (size_t)row0 * HID + col) = v0;
        *(__half2*)(attn_out + (size_t)(row0 + 8) * HID + col) = v1;
    }
}

// ---------------------------------------------------------------------------
extern "C" void kernel_launch(void* const* d_in, const int* in_sizes, int n_in,
                              void* d_out, int out_size) {
    const float* X  = (const float*)d_in[0];
    const float* Wq = (const float*)d_in[1];
    const float* Wk = (const float*)d_in[2];
    const float* Wv = (const float*)d_in[3];
    const float* Wo = (const float*)d_in[4];
    float* out = (float*)d_out;

    void* p;
    cudaGetSymbolAddress(&p, g_attnh);  __half* attnh = (__half*)p;
    cudaGetSymbolAddress(&p, g_Xh);     __half* Xh    = (__half*)p;
    cudaGetSymbolAddress(&p, g_Wqkvh);  __half* Wqkvh = (__half*)p;
    cudaGetSymbolAddress(&p, g_Woh);    __half* Woh   = (__half*)p;
    __half *Qh, *Kh, *Vh;
    cudaGetSymbolAddress(&p, g_Qh); Qh = (__half*)p;
    cudaGetSymbolAddress(&p, g_Kh); Kh = (__half*)p;
    cudaGetSymbolAddress(&p, g_Vh); Vh = (__half*)p;

    cudaFuncSetAttribute(gemm_o,   cudaFuncAttributeMaxDynamicSharedMemorySize, GEMM_SMEM);
    cudaFuncSetAttribute(gemm_qkv, cudaFuncAttributeMaxDynamicSharedMemorySize, QKV_SMEM);
    cudaFuncSetAttribute(flash_mma, cudaFuncAttributeMaxDynamicSharedMemorySize, FLASH_SMEM);

    // all conversions in one launch
    convert_all<<<(CONV_N4 + 255) / 256, 256>>>(
        (const float4*)Wq, (const float4*)Wk, (const float4*)Wv,
        (const float4*)Wo, (const float4*)X);

    // QKV projection: 64x128 CTAs, 3/SM, fused RoPE epilogue
    gemm_qkv<<<dim3(QKVW / 128, S_LEN / 64), 128, QKV_SMEM>>>(Xh, Wqkvh);

    // HMMA causal flash attention (single-fp16 K/V) -> fp16
    flash_mma<<<dim3(S_LEN / 64, NH), 128, FLASH_SMEM>>>(Qh, Kh, Vh, attnh);

    // Output projection (proven 49us config)
    gemm_o<<<dim3(HID / 128, S_LEN / 128), 256, GEMM_SMEM>>>(attnh, Woh, out, HID);
}